// round 8
// baseline (speedup 1.0000x reference)
#include <cuda_runtime.h>
#include <cstdint>

#define B_    256
#define T_    250
#define DIN   700
#define H1N   256
#define H2N   256
#define DOUT  20
#define BJ0   0.01f
#define BETA_ 1.8f
#define XPAD  704

// ---------------- device globals (no allocations allowed) ------------------
__device__ float          g_I1[B_ * T_ * H1N];      // x @ w_i2h1.T
__device__ float          g_Wt_i2h1[DIN * H1N];     // [d][j]
__device__ float2         g_Wpair[H1N * H1N];       // [k][j] = (w11, w12)
__device__ float          g_Wt22[H2N * H2N];        // [k][j]
__device__ float          g_Wt_h2o[H2N * DOUT];     // [k][o]
__device__ unsigned short g_xlist[B_ * T_ * XPAD];
__device__ int            g_xcnt[B_ * T_];

// ---------------- PTX helpers ----------------------------------------------
__device__ __forceinline__ uint32_t smem_u32(const void* p) {
    uint32_t a;
    asm("{ .reg .u64 t; cvta.to.shared.u64 t, %1; cvt.u32.u64 %0, t; }"
        : "=r"(a) : "l"(p));
    return a;
}
__device__ __forceinline__ uint32_t ctarank() {
    uint32_t r; asm("mov.u32 %0, %%cluster_ctarank;" : "=r"(r)); return r;
}
#define MBAR_INIT(addr, cnt) \
    asm volatile("mbarrier.init.shared.b64 [%0], %1;" :: "r"(addr), "r"(cnt) : "memory")
#define ST_CLUSTER_U32(laddr, rnk, val) \
    asm volatile("{ .reg .b32 ra; mapa.shared::cluster.u32 ra, %0, %1; " \
                 "st.shared::cluster.u32 [ra], %2; }" \
                 :: "r"(laddr), "r"(rnk), "r"(val) : "memory")
#define MBAR_ARRIVE_CLUSTER(laddr, rnk) \
    asm volatile("{ .reg .b32 ra; mapa.shared::cluster.u32 ra, %0, %1; " \
                 "mbarrier.arrive.release.cluster.shared::cluster.b64 _, [ra]; }" \
                 :: "r"(laddr), "r"(rnk) : "memory")
#define MBAR_WAIT_PARITY_CLUSTER(laddr, ph) do {                               \
    uint32_t _done = 0;                                                        \
    while (!_done) {                                                           \
        asm volatile("{ .reg .pred p; "                                        \
            "mbarrier.try_wait.parity.acquire.cluster.shared::cta.b64 p, [%1], %2, 0x989680; " \
            "selp.b32 %0, 1, 0, p; }"                                          \
            : "=r"(_done) : "r"(laddr), "r"(ph) : "memory");                   \
    }                                                                          \
} while (0)
#define CLUSTER_SYNC_() do {                                                   \
    asm volatile("barrier.cluster.arrive.aligned;" ::: "memory");              \
    asm volatile("barrier.cluster.wait.aligned;" ::: "memory");                \
} while (0)

// ---------------------------------------------------------------------------
// K0: weight transposes / interleaving
// ---------------------------------------------------------------------------
__global__ void prep_kernel(const float* __restrict__ wi,
                            const float* __restrict__ w11,
                            const float* __restrict__ w12,
                            const float* __restrict__ w22,
                            const float* __restrict__ wo) {
    int idx = blockIdx.x * blockDim.x + threadIdx.x;
    if (idx < H1N * DIN) {
        int r = idx / DIN, c = idx % DIN;
        g_Wt_i2h1[c * H1N + r] = wi[idx];
    }
    if (idx < H1N * H1N) {
        int r = idx / H1N, c = idx % H1N;
        g_Wpair[c * H1N + r] = make_float2(w11[idx], w12[idx]);
        g_Wt22[c * H1N + r]  = w22[idx];
    }
    if (idx < DOUT * H2N) {
        int r = idx / H2N, c = idx % H2N;
        g_Wt_h2o[c * DOUT + r] = wo[idx];
    }
}

// ---------------------------------------------------------------------------
// K0b: per-sample active-input lists (ascending d), one warp per sample
// ---------------------------------------------------------------------------
__global__ __launch_bounds__(256) void xlist_kernel(const float* __restrict__ x) {
    int s    = blockIdx.x * 8 + (threadIdx.x >> 5);
    int lane = threadIdx.x & 31;
    if (s >= B_ * T_) return;
    const float* xr = x + (size_t)s * DIN;
    int cnt = 0;
    for (int base = 0; base < DIN; base += 32) {
        int d = base + lane;
        float v = (d < DIN) ? xr[d] : 0.f;
        unsigned m = __ballot_sync(0xffffffffu, v != 0.f);
        if (v != 0.f)
            g_xlist[(size_t)s * XPAD + cnt + __popc(m & ((1u << lane) - 1u))] =
                (unsigned short)d;
        cnt += __popc(m);
    }
    if (lane == 0) g_xcnt[s] = cnt;
}

// ---------------------------------------------------------------------------
// K1: input projection, col-split smem weight tile (proven in R7).
// ---------------------------------------------------------------------------
__global__ __launch_bounds__(256, 2) void input_proj_kernel() {
    extern __shared__ float wt[];                 // [700][32]
    const int ct   = blockIdx.x;
    const int grp  = blockIdx.y;
    const int tid  = threadIdx.x;
    const int warp = tid >> 5;
    const int lane = tid & 31;

    for (int idx = tid; idx < DIN * 32; idx += 256) {
        int d = idx >> 5, c = idx & 31;
        wt[idx] = g_Wt_i2h1[d * H1N + ct * 32 + c];
    }
    __syncthreads();

    for (int si = 0; si < 80; si++) {
        const int s = grp * 640 + warp * 80 + si;
        const int n = g_xcnt[s];
        const unsigned short* ls = g_xlist + (size_t)s * XPAD;
        float acc = 0.f;
        int i = 0;
        for (; i + 4 <= n; i += 4) {
            ushort4 kk = *(const ushort4*)(ls + i);
            acc += wt[kk.x * 32 + lane];
            acc += wt[kk.y * 32 + lane];
            acc += wt[kk.z * 32 + lane];
            acc += wt[kk.w * 32 + lane];
        }
        for (; i < n; i++) acc += wt[ls[i] * 32 + lane];
        g_I1[(size_t)s * H1N + ct * 32 + lane] = acc;
    }
}

// ---------------------------------------------------------------------------
// K2: cluster-cooperative recurrent kernel, ONE exchange per step.
// Iteration t: LIF1(t) -> send (m1_t, m2_{t-1}) [8 aggregated arrives] ->
// wait -> mask-bit gathers: wpair over m1_t (-> s11_{t+1}, w12 part),
// w22 over m2_{t-1} (-> s22 for LIF2(t)), output for step t-1 (CTA rank b
// owns batch b's output) -> LIF2(t). Final output handled after the loop.
// All per-neuron sums strictly ascending-k (bitwise stable).
// ---------------------------------------------------------------------------
#define SM_WPAIR 0
#define SM_W22   65536
#define SM_STAGE 98304               // 16 u32
#define SM_MB    98368               // 2*8*16 u32 = 1024 B
#define SM_BAR   99392
#define SM_TOT   99408

__global__ __launch_bounds__(256, 2) __cluster_dims__(8, 1, 1)
void recurrent_kernel(
    const float* __restrict__ b_h1g, const float* __restrict__ b_h2g,
    const float* __restrict__ b_og,
    const float* __restrict__ tau_adp_h1, const float* __restrict__ tau_adp_h2,
    const float* __restrict__ tau_m_h1,  const float* __restrict__ tau_m_h2,
    const float* __restrict__ tau_m_o,
    float* __restrict__ out) {

    extern __shared__ __align__(16) char smraw[];
    float2*         wpair_s = (float2*)(smraw + SM_WPAIR);   // [k*32+c]
    float*          w22_s   = (float*)(smraw + SM_W22);      // [k*32+c]
    uint32_t*       stage   = (uint32_t*)(smraw + SM_STAGE); // [16]
    const uint32_t* mbw     = (const uint32_t*)(smraw + SM_MB);
    const uint32_t  smb     = smem_u32(smraw);
    const uint32_t  bar     = smb + SM_BAR;
    const uint32_t  mba     = smb + SM_MB;

    const int tid  = threadIdx.x;
    const int b    = tid >> 5;                 // warp = local batch
    const int c    = tid & 31;                 // lane = local column
    const uint32_t rank = ctarank();
    const int j    = rank * 32 + c;            // owned neuron
    const int gb   = (blockIdx.x >> 3) * 8 + b;

    // ---- load weight slices to smem
    for (int idx = tid; idx < H1N * 32; idx += 256) {
        int k = idx >> 5, cc = idx & 31;
        wpair_s[idx] = g_Wpair[k * H1N + rank * 32 + cc];
        w22_s[idx]   = g_Wt22[k * H1N + rank * 32 + cc];
    }
    if (tid == 0) MBAR_INIT(bar, 8);
    __syncthreads();
    CLUSTER_SYNC_();

    // ---- per-neuron params/state
    const float alpha1 = expf(-1.f / tau_m_h1[j]);
    const float ro1    = expf(-1.f / tau_adp_h1[j]);
    const float alpha2 = expf(-1.f / tau_m_h2[j]);
    const float ro2    = expf(-1.f / tau_adp_h2[j]);
    const float bh1    = b_h1g[j];
    const float bh2    = b_h2g[j];

    float mem1 = 0.f, spk1 = 0.f, bb1 = BJ0;
    float mem2 = 0.f, spk2 = 0.f, bb2 = BJ0;
    unsigned m2prev = 0u;

    // output ownership: CTA rank b handles batch b's output (warp b)
    const bool is_out = (rank == (uint32_t)b);
    float alpha_o = 0.f, bo = 0.f, mem_o = 0.f, acc_o = 0.f;
    if (is_out && c < DOUT) { alpha_o = expf(-1.f / tau_m_o[c]); bo = b_og[c]; }

    const float* I1row = g_I1 + (size_t)gb * T_ * H1N;
    float s11 = I1row[j] + bh1;                // t=0: no recurrent terms

    for (int t = 0; t < T_; t++) {
        const int par = t & 1;

        // ---- layer 1 LIF
        bb1  = ro1 * bb1 + BETA_ * (1.f - ro1) * spk1;
        mem1 = mem1 * alpha1 - bb1 * spk1 + (1.f - alpha1) * s11;
        spk1 = (mem1 - bb1 - BJ0 > 0.f) ? 1.f : 0.f;
        unsigned m1 = __ballot_sync(0xffffffffu, spk1 > 0.5f);

        if (c == 0) { stage[b] = m1; stage[8 + b] = m2prev; }
        __syncthreads();
        if (b == 0 && c < 8) {
            #pragma unroll
            for (int i = 0; i < 16; i++) {
                uint32_t la = mba + (par * 128 + rank * 16 + i) * 4;
                ST_CLUSTER_U32(la, (uint32_t)c, stage[i]);
            }
            MBAR_ARRIVE_CLUSTER(bar, (uint32_t)c);
        }
        MBAR_WAIT_PARITY_CLUSTER(bar, par);

        // ---- read masks (uniform per warp)
        const uint32_t* mb = mbw + par * 128;
        unsigned w1m[8], w2m[8];
        #pragma unroll
        for (int m = 0; m < 8; m++) {
            w1m[m] = mb[m * 16 + b];
            w2m[m] = mb[m * 16 + 8 + b];
        }

        // ---- pair gather over L1_t: w11 -> s11(t+1), w12 -> h2 part
        const int tn = (t + 1 < T_) ? (t + 1) : (T_ - 1);
        float a1 = I1row[tn * H1N + j] + bh1;
        float a2 = bh2;
        #pragma unroll
        for (int m = 0; m < 8; m++) {
            unsigned w = w1m[m];
            while (w) {
                int k = __ffs(w) - 1; w &= w - 1;
                float2 ww = wpair_s[(m * 32 + k) * 32 + c];
                a1 += ww.x; a2 += ww.y;
            }
        }

        // ---- w22 gather over L2_{t-1} -> s22 for LIF2(t)
        float a3 = 0.f;
        #pragma unroll
        for (int m = 0; m < 8; m++) {
            unsigned w = w2m[m];
            while (w) {
                int k = __ffs(w) - 1; w &= w - 1;
                a3 += w22_s[(m * 32 + k) * 32 + c];
            }
        }

        // ---- output + softmax for step t-1 (uses L2_{t-1})
        if (is_out && t > 0) {
            float oin = 0.f;
            if (c < DOUT) {
                oin = bo;
                #pragma unroll
                for (int m = 0; m < 8; m++) {
                    unsigned w = w2m[m];
                    while (w) {
                        int k = __ffs(w) - 1; w &= w - 1;
                        oin += g_Wt_h2o[(m * 32 + k) * DOUT + c];
                    }
                }
            }
            mem_o = mem_o * alpha_o + (1.f - alpha_o) * oin;
            float vv = (c < DOUT) ? mem_o : -1e30f;
            float mx = vv;
            #pragma unroll
            for (int s = 16; s > 0; s >>= 1)
                mx = fmaxf(mx, __shfl_xor_sync(0xffffffffu, mx, s));
            float e = (c < DOUT) ? expf(vv - mx) : 0.f;
            float sm = e;
            #pragma unroll
            for (int s = 16; s > 0; s >>= 1)
                sm += __shfl_xor_sync(0xffffffffu, sm, s);
            if (c < DOUT) acc_o += e / sm;
        }

        // ---- layer 2 LIF (step t)
        float h2 = a2 + a3;
        bb2  = ro2 * bb2 + BETA_ * (1.f - ro2) * spk2;
        mem2 = mem2 * alpha2 - bb2 * spk2 + (1.f - alpha2) * h2;
        spk2 = (mem2 - bb2 - BJ0 > 0.f) ? 1.f : 0.f;
        m2prev = __ballot_sync(0xffffffffu, spk2 > 0.5f);

        s11 = a1;
    }

    // ---- final exchange: output for step T-1 (L2_{249})
    {
        const int par = T_ & 1;   // 0
        if (c == 0) { stage[b] = 0u; stage[8 + b] = m2prev; }
        __syncthreads();
        if (b == 0 && c < 8) {
            #pragma unroll
            for (int i = 0; i < 16; i++) {
                uint32_t la = mba + (par * 128 + rank * 16 + i) * 4;
                ST_CLUSTER_U32(la, (uint32_t)c, stage[i]);
            }
            MBAR_ARRIVE_CLUSTER(bar, (uint32_t)c);
        }
        MBAR_WAIT_PARITY_CLUSTER(bar, par);

        if (is_out) {
            const uint32_t* mb = mbw + par * 128;
            float oin = 0.f;
            if (c < DOUT) {
                oin = bo;
                #pragma unroll
                for (int m = 0; m < 8; m++) {
                    unsigned w = mb[m * 16 + 8 + b];
                    while (w) {
                        int k = __ffs(w) - 1; w &= w - 1;
                        oin += g_Wt_h2o[(m * 32 + k) * DOUT + c];
                    }
                }
            }
            mem_o = mem_o * alpha_o + (1.f - alpha_o) * oin;
            float vv = (c < DOUT) ? mem_o : -1e30f;
            float mx = vv;
            #pragma unroll
            for (int s = 16; s > 0; s >>= 1)
                mx = fmaxf(mx, __shfl_xor_sync(0xffffffffu, mx, s));
            float e = (c < DOUT) ? expf(vv - mx) : 0.f;
            float sm = e;
            #pragma unroll
            for (int s = 16; s > 0; s >>= 1)
                sm += __shfl_xor_sync(0xffffffffu, sm, s);
            if (c < DOUT) acc_o += e / sm;
            if (c < DOUT) out[gb * DOUT + c] = acc_o;
        }
    }
    CLUSTER_SYNC_();
}

// ---------------------------------------------------------------------------
extern "C" void kernel_launch(void* const* d_in, const int* in_sizes, int n_in,
                              void* d_out, int out_size) {
    const float* x          = (const float*)d_in[0];
    const float* w_i2h1     = (const float*)d_in[1];
    const float* w_h12h1    = (const float*)d_in[2];
    const float* w_h12h2    = (const float*)d_in[3];
    const float* w_h22h2    = (const float*)d_in[4];
    const float* w_h2o      = (const float*)d_in[5];
    const float* b_h1       = (const float*)d_in[6];
    const float* b_h2       = (const float*)d_in[7];
    const float* b_o        = (const float*)d_in[8];
    const float* tau_adp_h1 = (const float*)d_in[9];
    const float* tau_adp_h2 = (const float*)d_in[10];
    const float* tau_m_h1   = (const float*)d_in[11];
    const float* tau_m_h2   = (const float*)d_in[12];
    const float* tau_m_o    = (const float*)d_in[13];

    cudaFuncSetAttribute(input_proj_kernel,
                         cudaFuncAttributeMaxDynamicSharedMemorySize, DIN * 32 * 4);
    cudaFuncSetAttribute(recurrent_kernel,
                         cudaFuncAttributeMaxDynamicSharedMemorySize, SM_TOT);

    prep_kernel<<<(H1N * DIN + 255) / 256, 256>>>(w_i2h1, w_h12h1, w_h12h2,
                                                  w_h22h2, w_h2o);
    xlist_kernel<<<(B_ * T_) / 8, 256>>>(x);
    input_proj_kernel<<<dim3(8, 100), 256, DIN * 32 * 4>>>();
    recurrent_kernel<<<B_, 256, SM_TOT>>>(b_h1, b_h2, b_o,
                                          tau_adp_h1, tau_adp_h2,
                                          tau_m_h1, tau_m_h2, tau_m_o,
                                          (float*)d_out);
}

// round 9
// speedup vs baseline: 1.2235x; 1.2235x over previous
#include <cuda_runtime.h>
#include <cstdint>

#define B_    256
#define T_    250
#define DIN   700
#define H1N   256
#define H2N   256
#define DOUT  20
#define BJ0   0.01f
#define BETA_ 1.8f
#define XPAD  704

// ---------------- device globals (no allocations allowed) ------------------
__device__ float          g_I1[B_ * T_ * H1N];      // x @ w_i2h1.T
__device__ float          g_Wt_i2h1[DIN * H1N];     // [d][j]
__device__ float2         g_Wpair[H1N * H1N];       // [k][j] = (w11, w12)
__device__ float          g_Wt22[H2N * H2N];        // [k][j]
__device__ float          g_Wt_h2o[H2N * DOUT];     // [k][o]
__device__ unsigned short g_xlist[B_ * T_ * XPAD];
__device__ int            g_xcnt[B_ * T_];

// ---------------- PTX helpers ----------------------------------------------
__device__ __forceinline__ uint32_t smem_u32(const void* p) {
    uint32_t a;
    asm("{ .reg .u64 t; cvta.to.shared.u64 t, %1; cvt.u32.u64 %0, t; }"
        : "=r"(a) : "l"(p));
    return a;
}
__device__ __forceinline__ uint32_t ctarank() {
    uint32_t r; asm("mov.u32 %0, %%cluster_ctarank;" : "=r"(r)); return r;
}
#define MBAR_INIT(addr, cnt) \
    asm volatile("mbarrier.init.shared.b64 [%0], %1;" :: "r"(addr), "r"(cnt) : "memory")
#define ST_CLUSTER_V4(laddr, rnk, v) \
    asm volatile("{ .reg .b32 ra; mapa.shared::cluster.u32 ra, %0, %1; " \
                 "st.shared::cluster.v4.b32 [ra], {%2,%3,%4,%5}; }" \
                 :: "r"(laddr), "r"(rnk), "r"(v.x), "r"(v.y), "r"(v.z), "r"(v.w) \
                 : "memory")
#define MBAR_ARRIVE_CLUSTER(laddr, rnk) \
    asm volatile("{ .reg .b32 ra; mapa.shared::cluster.u32 ra, %0, %1; " \
                 "mbarrier.arrive.release.cluster.shared::cluster.b64 _, [ra]; }" \
                 :: "r"(laddr), "r"(rnk) : "memory")
#define MBAR_WAIT_PARITY_CLUSTER(laddr, ph) do {                               \
    uint32_t _done = 0;                                                        \
    while (!_done) {                                                           \
        asm volatile("{ .reg .pred p; "                                        \
            "mbarrier.try_wait.parity.acquire.cluster.shared::cta.b64 p, [%1], %2, 0x989680; " \
            "selp.b32 %0, 1, 0, p; }"                                          \
            : "=r"(_done) : "r"(laddr), "r"(ph) : "memory");                   \
    }                                                                          \
} while (0)
#define CLUSTER_SYNC_() do {                                                   \
    asm volatile("barrier.cluster.arrive.aligned;" ::: "memory");              \
    asm volatile("barrier.cluster.wait.aligned;" ::: "memory");                \
} while (0)

// ---------------------------------------------------------------------------
// K0: weight transposes / interleaving
// ---------------------------------------------------------------------------
__global__ void prep_kernel(const float* __restrict__ wi,
                            const float* __restrict__ w11,
                            const float* __restrict__ w12,
                            const float* __restrict__ w22,
                            const float* __restrict__ wo) {
    int idx = blockIdx.x * blockDim.x + threadIdx.x;
    if (idx < H1N * DIN) {
        int r = idx / DIN, c = idx % DIN;
        g_Wt_i2h1[c * H1N + r] = wi[idx];
    }
    if (idx < H1N * H1N) {
        int r = idx / H1N, c = idx % H1N;
        g_Wpair[c * H1N + r] = make_float2(w11[idx], w12[idx]);
        g_Wt22[c * H1N + r]  = w22[idx];
    }
    if (idx < DOUT * H2N) {
        int r = idx / H2N, c = idx % H2N;
        g_Wt_h2o[c * DOUT + r] = wo[idx];
    }
}

// ---------------------------------------------------------------------------
// K0b: per-sample active-input lists (ascending d), one warp per sample
// ---------------------------------------------------------------------------
__global__ __launch_bounds__(256) void xlist_kernel(const float* __restrict__ x) {
    int s    = blockIdx.x * 8 + (threadIdx.x >> 5);
    int lane = threadIdx.x & 31;
    if (s >= B_ * T_) return;
    const float* xr = x + (size_t)s * DIN;
    int cnt = 0;
    for (int base = 0; base < DIN; base += 32) {
        int d = base + lane;
        float v = (d < DIN) ? xr[d] : 0.f;
        unsigned m = __ballot_sync(0xffffffffu, v != 0.f);
        if (v != 0.f)
            g_xlist[(size_t)s * XPAD + cnt + __popc(m & ((1u << lane) - 1u))] =
                (unsigned short)d;
        cnt += __popc(m);
    }
    if (lane == 0) g_xcnt[s] = cnt;
}

// ---------------------------------------------------------------------------
// K1: input projection, col-split smem weight tile (proven in R7).
// ---------------------------------------------------------------------------
__global__ __launch_bounds__(256, 2) void input_proj_kernel() {
    extern __shared__ float wt[];                 // [700][32]
    const int ct   = blockIdx.x;
    const int grp  = blockIdx.y;
    const int tid  = threadIdx.x;
    const int warp = tid >> 5;
    const int lane = tid & 31;

    for (int idx = tid; idx < DIN * 32; idx += 256) {
        int d = idx >> 5, c = idx & 31;
        wt[idx] = g_Wt_i2h1[d * H1N + ct * 32 + c];
    }
    __syncthreads();

    for (int si = 0; si < 80; si++) {
        const int s = grp * 640 + warp * 80 + si;
        const int n = g_xcnt[s];
        const unsigned short* ls = g_xlist + (size_t)s * XPAD;
        float acc = 0.f;
        int i = 0;
        for (; i + 4 <= n; i += 4) {
            ushort4 kk = *(const ushort4*)(ls + i);
            acc += wt[kk.x * 32 + lane];
            acc += wt[kk.y * 32 + lane];
            acc += wt[kk.z * 32 + lane];
            acc += wt[kk.w * 32 + lane];
        }
        for (; i < n; i++) acc += wt[ls[i] * 32 + lane];
        g_I1[(size_t)s * H1N + ct * 32 + lane] = acc;
    }
}

// ---------------------------------------------------------------------------
// K2: cluster-cooperative recurrent kernel.
// Single exchange per step (ships m1_t and m2_{t-1} together, 8 aggregated
// arrivals, v4 funnel stores). List-based gathers (ascending k, bitwise
// stable). Output for step t-1 handled by CTA rank b (batch b): its LDG
// gather is issued BEFORE the smem gathers so L2 latency overlaps LDS work;
// softmax finalizes after the w22 gather. Final step drains after the loop.
// ---------------------------------------------------------------------------
#define SM_WPAIR 0
#define SM_W22   65536
#define SM_L1    98304               // 8 * 256 bytes
#define SM_L2    100352              // 8 * 256 bytes
#define SM_STAGE 102400              // 16 u32 (16B aligned)
#define SM_MB    102464              // 2*8*16 u32 = 1024 B
#define SM_BAR   103488
#define SM_TOT   103504

__global__ __launch_bounds__(256, 2) __cluster_dims__(8, 1, 1)
void recurrent_kernel(
    const float* __restrict__ b_h1g, const float* __restrict__ b_h2g,
    const float* __restrict__ b_og,
    const float* __restrict__ tau_adp_h1, const float* __restrict__ tau_adp_h2,
    const float* __restrict__ tau_m_h1,  const float* __restrict__ tau_m_h2,
    const float* __restrict__ tau_m_o,
    float* __restrict__ out) {

    extern __shared__ __align__(16) char smraw[];
    float2*         wpair_s = (float2*)(smraw + SM_WPAIR);   // [k*32+c]
    float*          w22_s   = (float*)(smraw + SM_W22);      // [k*32+c]
    uint8_t*        L1s     = (uint8_t*)(smraw + SM_L1);     // [b][256]
    uint8_t*        L2s     = (uint8_t*)(smraw + SM_L2);
    uint32_t*       stage   = (uint32_t*)(smraw + SM_STAGE); // [16]
    const uint32_t* mbw     = (const uint32_t*)(smraw + SM_MB);
    const uint32_t  smb     = smem_u32(smraw);
    const uint32_t  bar     = smb + SM_BAR;
    const uint32_t  mba     = smb + SM_MB;

    const int tid  = threadIdx.x;
    const int b    = tid >> 5;                 // warp = local batch
    const int c    = tid & 31;                 // lane = local column
    const uint32_t rank = ctarank();
    const int j    = rank * 32 + c;            // owned neuron
    const int gb   = (blockIdx.x >> 3) * 8 + b;

    // ---- load weight slices to smem
    for (int idx = tid; idx < H1N * 32; idx += 256) {
        int k = idx >> 5, cc = idx & 31;
        wpair_s[idx] = g_Wpair[k * H1N + rank * 32 + cc];
        w22_s[idx]   = g_Wt22[k * H1N + rank * 32 + cc];
    }
    if (tid == 0) MBAR_INIT(bar, 8);
    __syncthreads();
    CLUSTER_SYNC_();

    // ---- per-neuron params/state
    const float alpha1 = expf(-1.f / tau_m_h1[j]);
    const float ro1    = expf(-1.f / tau_adp_h1[j]);
    const float alpha2 = expf(-1.f / tau_m_h2[j]);
    const float ro2    = expf(-1.f / tau_adp_h2[j]);
    const float bh1    = b_h1g[j];
    const float bh2    = b_h2g[j];

    float mem1 = 0.f, spk1 = 0.f, bb1 = BJ0;
    float mem2 = 0.f, spk2 = 0.f, bb2 = BJ0;
    unsigned m2prev = 0u;

    // output ownership: CTA rank b handles batch b (one owner warp per CTA)
    const bool is_out = (rank == (uint32_t)b);
    float alpha_o = 0.f, bo = 0.f, mem_o = 0.f, acc_o = 0.f;
    if (is_out && c < DOUT) { alpha_o = expf(-1.f / tau_m_o[c]); bo = b_og[c]; }

    const float* I1row = g_I1 + (size_t)gb * T_ * H1N;
    float s11 = I1row[j] + bh1;                // t=0: no recurrent terms

    uint8_t* L1b = L1s + b * 256;
    uint8_t* L2b = L2s + b * 256;

    for (int t = 0; t < T_; t++) {
        const int par = t & 1;

        // ---- layer 1 LIF (step t)
        bb1  = ro1 * bb1 + BETA_ * (1.f - ro1) * spk1;
        mem1 = mem1 * alpha1 - bb1 * spk1 + (1.f - alpha1) * s11;
        spk1 = (mem1 - bb1 - BJ0 > 0.f) ? 1.f : 0.f;
        unsigned m1 = __ballot_sync(0xffffffffu, spk1 > 0.5f);

        if (c == 0) { stage[b] = m1; stage[8 + b] = m2prev; }
        __syncthreads();

        // prefetch next step's input projection while exchange is in flight
        const int tn = (t + 1 < T_) ? (t + 1) : (T_ - 1);
        const float i1n = I1row[tn * H1N + j];

        if (b == 0 && c < 8) {
            const uint4* st4 = (const uint4*)stage;
            #pragma unroll
            for (int i = 0; i < 4; i++) {
                uint4 v = st4[i];
                uint32_t la = mba + (par * 128 + rank * 16 + i * 4) * 4;
                ST_CLUSTER_V4(la, (uint32_t)c, v);
            }
            MBAR_ARRIVE_CLUSTER(bar, (uint32_t)c);
        }
        MBAR_WAIT_PARITY_CLUSTER(bar, par);

        const uint32_t* mb = mbw + par * 128;

        // ---- build L2_{t-1} list, then L1_t list (ascending neuron index)
        int n2 = 0;
        #pragma unroll
        for (int m = 0; m < 8; m++) {
            unsigned w = mb[m * 16 + 8 + b];
            if (w & (1u << c))
                L2b[n2 + __popc(w & ((1u << c) - 1u))] = (uint8_t)(m * 32 + c);
            n2 += __popc(w);
        }
        int n1 = 0;
        #pragma unroll
        for (int m = 0; m < 8; m++) {
            unsigned w = mb[m * 16 + b];
            if (w & (1u << c))
                L1b[n1 + __popc(w & ((1u << c) - 1u))] = (uint8_t)(m * 32 + c);
            n1 += __popc(w);
        }
        __syncwarp();

        // ---- output gather for step t-1 (LDG, issued early to overlap)
        float oin = 0.f;
        if (is_out && t > 0 && c < DOUT) {
            oin = bo;
            int i = 0;
            for (; i + 4 <= n2; i += 4) {
                unsigned kk = *(const unsigned*)(L2b + i);
                float w0 = g_Wt_h2o[(kk & 255u) * DOUT + c];
                float w1 = g_Wt_h2o[((kk >> 8) & 255u) * DOUT + c];
                float w2 = g_Wt_h2o[((kk >> 16) & 255u) * DOUT + c];
                float w3 = g_Wt_h2o[(kk >> 24) * DOUT + c];
                oin += w0; oin += w1; oin += w2; oin += w3;
            }
            for (; i < n2; i++) oin += g_Wt_h2o[L2b[i] * DOUT + c];
        }

        // ---- pair gather over L1_t: w11 -> s11(t+1), w12 -> h2 part (smem)
        float a1 = i1n + bh1;
        float a2 = bh2;
        {
            int i = 0;
            for (; i + 4 <= n1; i += 4) {
                unsigned kk = *(const unsigned*)(L1b + i);
                float2 w0 = wpair_s[(kk & 255u) * 32 + c];
                float2 w1 = wpair_s[((kk >> 8) & 255u) * 32 + c];
                float2 w2 = wpair_s[((kk >> 16) & 255u) * 32 + c];
                float2 w3 = wpair_s[(kk >> 24) * 32 + c];
                a1 += w0.x; a2 += w0.y;
                a1 += w1.x; a2 += w1.y;
                a1 += w2.x; a2 += w2.y;
                a1 += w3.x; a2 += w3.y;
            }
            for (; i < n1; i++) {
                float2 w = wpair_s[L1b[i] * 32 + c];
                a1 += w.x; a2 += w.y;
            }
        }

        // ---- w22 gather over L2_{t-1} -> s22 for LIF2(t) (smem)
        float a3 = 0.f;
        {
            int i = 0;
            for (; i + 4 <= n2; i += 4) {
                unsigned kk = *(const unsigned*)(L2b + i);
                float w0 = w22_s[(kk & 255u) * 32 + c];
                float w1 = w22_s[((kk >> 8) & 255u) * 32 + c];
                float w2 = w22_s[((kk >> 16) & 255u) * 32 + c];
                float w3 = w22_s[(kk >> 24) * 32 + c];
                a3 += w0; a3 += w1; a3 += w2; a3 += w3;
            }
            for (; i < n2; i++) a3 += w22_s[L2b[i] * 32 + c];
        }

        // ---- finalize output for step t-1 (softmax accumulate)
        if (is_out && t > 0) {
            mem_o = mem_o * alpha_o + (1.f - alpha_o) * oin;
            float vv = (c < DOUT) ? mem_o : -1e30f;
            float mx = vv;
            #pragma unroll
            for (int s = 16; s > 0; s >>= 1)
                mx = fmaxf(mx, __shfl_xor_sync(0xffffffffu, mx, s));
            float e = (c < DOUT) ? expf(vv - mx) : 0.f;
            float sm = e;
            #pragma unroll
            for (int s = 16; s > 0; s >>= 1)
                sm += __shfl_xor_sync(0xffffffffu, sm, s);
            if (c < DOUT) acc_o += e / sm;
        }

        // ---- layer 2 LIF (step t)
        float h2 = a2 + a3;
        bb2  = ro2 * bb2 + BETA_ * (1.f - ro2) * spk2;
        mem2 = mem2 * alpha2 - bb2 * spk2 + (1.f - alpha2) * h2;
        spk2 = (mem2 - bb2 - BJ0 > 0.f) ? 1.f : 0.f;
        m2prev = __ballot_sync(0xffffffffu, spk2 > 0.5f);

        s11 = a1;
    }

    // ---- drain exchange: output for step T-1 (uses m2_{249})
    {
        const int par = T_ & 1;      // 0
        if (c == 0) { stage[b] = 0u; stage[8 + b] = m2prev; }
        __syncthreads();
        if (b == 0 && c < 8) {
            const uint4* st4 = (const uint4*)stage;
            #pragma unroll
            for (int i = 0; i < 4; i++) {
                uint4 v = st4[i];
                uint32_t la = mba + (par * 128 + rank * 16 + i * 4) * 4;
                ST_CLUSTER_V4(la, (uint32_t)c, v);
            }
            MBAR_ARRIVE_CLUSTER(bar, (uint32_t)c);
        }
        MBAR_WAIT_PARITY_CLUSTER(bar, par);

        if (is_out) {
            const uint32_t* mb = mbw + par * 128;
            int n2 = 0;
            #pragma unroll
            for (int m = 0; m < 8; m++) {
                unsigned w = mb[m * 16 + 8 + b];
                if (w & (1u << c))
                    L2b[n2 + __popc(w & ((1u << c) - 1u))] = (uint8_t)(m * 32 + c);
                n2 += __popc(w);
            }
            __syncwarp();
            float oin = 0.f;
            if (c < DOUT) {
                oin = bo;
                int i = 0;
                for (; i + 4 <= n2; i += 4) {
                    unsigned kk = *(const unsigned*)(L2b + i);
                    float w0 = g_Wt_h2o[(kk & 255u) * DOUT + c];
                    float w1 = g_Wt_h2o[((kk >> 8) & 255u) * DOUT + c];
                    float w2 = g_Wt_h2o[((kk >> 16) & 255u) * DOUT + c];
                    float w3 = g_Wt_h2o[(kk >> 24) * DOUT + c];
                    oin += w0; oin += w1; oin += w2; oin += w3;
                }
                for (; i < n2; i++) oin += g_Wt_h2o[L2b[i] * DOUT + c];
            }
            mem_o = mem_o * alpha_o + (1.f - alpha_o) * oin;
            float vv = (c < DOUT) ? mem_o : -1e30f;
            float mx = vv;
            #pragma unroll
            for (int s = 16; s > 0; s >>= 1)
                mx = fmaxf(mx, __shfl_xor_sync(0xffffffffu, mx, s));
            float e = (c < DOUT) ? expf(vv - mx) : 0.f;
            float sm = e;
            #pragma unroll
            for (int s = 16; s > 0; s >>= 1)
                sm += __shfl_xor_sync(0xffffffffu, sm, s);
            if (c < DOUT) { acc_o += e / sm; out[gb * DOUT + c] = acc_o; }
        }
    }
    CLUSTER_SYNC_();
}

// ---------------------------------------------------------------------------
extern "C" void kernel_launch(void* const* d_in, const int* in_sizes, int n_in,
                              void* d_out, int out_size) {
    const float* x          = (const float*)d_in[0];
    const float* w_i2h1     = (const float*)d_in[1];
    const float* w_h12h1    = (const float*)d_in[2];
    const float* w_h12h2    = (const float*)d_in[3];
    const float* w_h22h2    = (const float*)d_in[4];
    const float* w_h2o      = (const float*)d_in[5];
    const float* b_h1       = (const float*)d_in[6];
    const float* b_h2       = (const float*)d_in[7];
    const float* b_o        = (const float*)d_in[8];
    const float* tau_adp_h1 = (const float*)d_in[9];
    const float* tau_adp_h2 = (const float*)d_in[10];
    const float* tau_m_h1   = (const float*)d_in[11];
    const float* tau_m_h2   = (const float*)d_in[12];
    const float* tau_m_o    = (const float*)d_in[13];

    cudaFuncSetAttribute(input_proj_kernel,
                         cudaFuncAttributeMaxDynamicSharedMemorySize, DIN * 32 * 4);
    cudaFuncSetAttribute(recurrent_kernel,
                         cudaFuncAttributeMaxDynamicSharedMemorySize, SM_TOT);

    prep_kernel<<<(H1N * DIN + 255) / 256, 256>>>(w_i2h1, w_h12h1, w_h12h2,
                                                  w_h22h2, w_h2o);
    xlist_kernel<<<(B_ * T_) / 8, 256>>>(x);
    input_proj_kernel<<<dim3(8, 100), 256, DIN * 32 * 4>>>();
    recurrent_kernel<<<B_, 256, SM_TOT>>>(b_h1, b_h2, b_o,
                                          tau_adp_h1, tau_adp_h2,
                                          tau_m_h1, tau_m_h2, tau_m_o,
                                          (float*)d_out);
}

// round 10
// speedup vs baseline: 1.3016x; 1.0638x over previous
#include <cuda_runtime.h>
#include <cstdint>

#define B_    256
#define T_    250
#define DIN   700
#define H1N   256
#define H2N   256
#define DOUT  20
#define BJ0   0.01f
#define BETA_ 1.8f
#define XPAD  704

// ---------------- device globals (no allocations allowed) ------------------
__device__ float          g_I1[B_ * T_ * H1N];      // x @ w_i2h1.T
__device__ float          g_Wt_i2h1[DIN * H1N];     // [d][j]
__device__ float2         g_Wpair[H1N * H1N];       // [k][j] = (w11, w12)
__device__ float          g_Wt22[H2N * H2N];        // [k][j]
__device__ float          g_Wt_h2o[H2N * DOUT];     // [k][o]
__device__ unsigned short g_xlist[B_ * T_ * XPAD];
__device__ int            g_xcnt[B_ * T_];
__device__ uint32_t       g_m2[B_ * T_ * 8];        // layer-2 spike masks
__device__ float          g_oin[B_ * T_ * DOUT];    // output drives

// ---------------- PTX helpers ----------------------------------------------
__device__ __forceinline__ uint32_t smem_u32(const void* p) {
    uint32_t a;
    asm("{ .reg .u64 t; cvta.to.shared.u64 t, %1; cvt.u32.u64 %0, t; }"
        : "=r"(a) : "l"(p));
    return a;
}
__device__ __forceinline__ uint32_t ctarank() {
    uint32_t r; asm("mov.u32 %0, %%cluster_ctarank;" : "=r"(r)); return r;
}
#define MBAR_INIT(addr, cnt) \
    asm volatile("mbarrier.init.shared.b64 [%0], %1;" :: "r"(addr), "r"(cnt) : "memory")
#define ST_CLUSTER_V4(laddr, rnk, v) \
    asm volatile("{ .reg .b32 ra; mapa.shared::cluster.u32 ra, %0, %1; " \
                 "st.shared::cluster.v4.b32 [ra], {%2,%3,%4,%5}; }" \
                 :: "r"(laddr), "r"(rnk), "r"(v.x), "r"(v.y), "r"(v.z), "r"(v.w) \
                 : "memory")
#define MBAR_ARRIVE_CLUSTER(laddr, rnk) \
    asm volatile("{ .reg .b32 ra; mapa.shared::cluster.u32 ra, %0, %1; " \
                 "mbarrier.arrive.release.cluster.shared::cluster.b64 _, [ra]; }" \
                 :: "r"(laddr), "r"(rnk) : "memory")
#define MBAR_WAIT_PARITY_CLUSTER(laddr, ph) do {                               \
    uint32_t _done = 0;                                                        \
    while (!_done) {                                                           \
        asm volatile("{ .reg .pred p; "                                        \
            "mbarrier.try_wait.parity.acquire.cluster.shared::cta.b64 p, [%1], %2, 0x989680; " \
            "selp.b32 %0, 1, 0, p; }"                                          \
            : "=r"(_done) : "r"(laddr), "r"(ph) : "memory");                   \
    }                                                                          \
} while (0)
#define CLUSTER_SYNC_() do {                                                   \
    asm volatile("barrier.cluster.arrive.aligned;" ::: "memory");              \
    asm volatile("barrier.cluster.wait.aligned;" ::: "memory");                \
} while (0)

// ---------------------------------------------------------------------------
// K0: weight transposes / interleaving
// ---------------------------------------------------------------------------
__global__ void prep_kernel(const float* __restrict__ wi,
                            const float* __restrict__ w11,
                            const float* __restrict__ w12,
                            const float* __restrict__ w22,
                            const float* __restrict__ wo) {
    int idx = blockIdx.x * blockDim.x + threadIdx.x;
    if (idx < H1N * DIN) {
        int r = idx / DIN, c = idx % DIN;
        g_Wt_i2h1[c * H1N + r] = wi[idx];
    }
    if (idx < H1N * H1N) {
        int r = idx / H1N, c = idx % H1N;
        g_Wpair[c * H1N + r] = make_float2(w11[idx], w12[idx]);
        g_Wt22[c * H1N + r]  = w22[idx];
    }
    if (idx < DOUT * H2N) {
        int r = idx / H2N, c = idx % H2N;
        g_Wt_h2o[c * DOUT + r] = wo[idx];
    }
}

// ---------------------------------------------------------------------------
// K0b: per-sample active-input lists (ascending d), one warp per sample
// ---------------------------------------------------------------------------
__global__ __launch_bounds__(256) void xlist_kernel(const float* __restrict__ x) {
    int s    = blockIdx.x * 8 + (threadIdx.x >> 5);
    int lane = threadIdx.x & 31;
    if (s >= B_ * T_) return;
    const float* xr = x + (size_t)s * DIN;
    int cnt = 0;
    for (int base = 0; base < DIN; base += 32) {
        int d = base + lane;
        float v = (d < DIN) ? xr[d] : 0.f;
        unsigned m = __ballot_sync(0xffffffffu, v != 0.f);
        if (v != 0.f)
            g_xlist[(size_t)s * XPAD + cnt + __popc(m & ((1u << lane) - 1u))] =
                (unsigned short)d;
        cnt += __popc(m);
    }
    if (lane == 0) g_xcnt[s] = cnt;
}

// ---------------------------------------------------------------------------
// K1: input projection, col-split smem weight tile. 4-way split accumulators
// (chains broken; reassociation only — ~1e-7 perturbation).
// ---------------------------------------------------------------------------
__global__ __launch_bounds__(256, 2) void input_proj_kernel() {
    extern __shared__ float wt[];                 // [700][32]
    const int ct   = blockIdx.x;
    const int grp  = blockIdx.y;
    const int tid  = threadIdx.x;
    const int warp = tid >> 5;
    const int lane = tid & 31;

    for (int idx = tid; idx < DIN * 32; idx += 256) {
        int d = idx >> 5, c = idx & 31;
        wt[idx] = g_Wt_i2h1[d * H1N + ct * 32 + c];
    }
    __syncthreads();

    for (int si = 0; si < 80; si++) {
        const int s = grp * 640 + warp * 80 + si;
        const int n = g_xcnt[s];
        const unsigned short* ls = g_xlist + (size_t)s * XPAD;
        float p0 = 0.f, p1 = 0.f, p2 = 0.f, p3 = 0.f;
        int i = 0;
        for (; i + 4 <= n; i += 4) {
            ushort4 kk = *(const ushort4*)(ls + i);
            p0 += wt[kk.x * 32 + lane];
            p1 += wt[kk.y * 32 + lane];
            p2 += wt[kk.z * 32 + lane];
            p3 += wt[kk.w * 32 + lane];
        }
        for (; i < n; i++) p0 += wt[ls[i] * 32 + lane];
        g_I1[(size_t)s * H1N + ct * 32 + lane] = (p0 + p1) + (p2 + p3);
    }
}

// ---------------------------------------------------------------------------
// K2: cluster-cooperative recurrent kernel. Single exchange per step; all
// warps symmetric (output path offloaded to K3). 4-way split accumulators.
// Each step stores the m2 ballot word to global (fire-and-forget).
// ---------------------------------------------------------------------------
#define SM_WPAIR 0
#define SM_W22   65536
#define SM_L1    98304               // 8 * 256 bytes
#define SM_L2    100352              // 8 * 256 bytes
#define SM_STAGE 102400              // 16 u32 (16B aligned)
#define SM_MB    102464              // 2*8*16 u32 = 1024 B
#define SM_BAR   103488
#define SM_TOT   103504

__global__ __launch_bounds__(256, 2) __cluster_dims__(8, 1, 1)
void recurrent_kernel(
    const float* __restrict__ b_h1g, const float* __restrict__ b_h2g,
    const float* __restrict__ tau_adp_h1, const float* __restrict__ tau_adp_h2,
    const float* __restrict__ tau_m_h1,  const float* __restrict__ tau_m_h2) {

    extern __shared__ __align__(16) char smraw[];
    float2*         wpair_s = (float2*)(smraw + SM_WPAIR);   // [k*32+c]
    float*          w22_s   = (float*)(smraw + SM_W22);      // [k*32+c]
    uint8_t*        L1s     = (uint8_t*)(smraw + SM_L1);     // [b][256]
    uint8_t*        L2s     = (uint8_t*)(smraw + SM_L2);
    uint32_t*       stage   = (uint32_t*)(smraw + SM_STAGE); // [16]
    const uint32_t* mbw     = (const uint32_t*)(smraw + SM_MB);
    const uint32_t  smb     = smem_u32(smraw);
    const uint32_t  bar     = smb + SM_BAR;
    const uint32_t  mba     = smb + SM_MB;

    const int tid  = threadIdx.x;
    const int b    = tid >> 5;                 // warp = local batch
    const int c    = tid & 31;                 // lane = local column
    const uint32_t rank = ctarank();
    const int j    = rank * 32 + c;            // owned neuron
    const int gb   = (blockIdx.x >> 3) * 8 + b;

    // ---- load weight slices to smem
    for (int idx = tid; idx < H1N * 32; idx += 256) {
        int k = idx >> 5, cc = idx & 31;
        wpair_s[idx] = g_Wpair[k * H1N + rank * 32 + cc];
        w22_s[idx]   = g_Wt22[k * H1N + rank * 32 + cc];
    }
    if (tid == 0) MBAR_INIT(bar, 8);
    __syncthreads();
    CLUSTER_SYNC_();

    // ---- per-neuron params/state
    const float alpha1 = expf(-1.f / tau_m_h1[j]);
    const float ro1    = expf(-1.f / tau_adp_h1[j]);
    const float alpha2 = expf(-1.f / tau_m_h2[j]);
    const float ro2    = expf(-1.f / tau_adp_h2[j]);
    const float bh1    = b_h1g[j];
    const float bh2    = b_h2g[j];

    float mem1 = 0.f, spk1 = 0.f, bb1 = BJ0;
    float mem2 = 0.f, spk2 = 0.f, bb2 = BJ0;
    unsigned m2prev = 0u;

    const float* I1row = g_I1 + (size_t)gb * T_ * H1N;
    float s11 = I1row[j] + bh1;                // t=0: no recurrent terms

    uint8_t* L1b = L1s + b * 256;
    uint8_t* L2b = L2s + b * 256;
    uint32_t* m2out = g_m2 + (size_t)gb * T_ * 8 + rank;

    for (int t = 0; t < T_; t++) {
        const int par = t & 1;

        // ---- layer 1 LIF (step t)
        bb1  = ro1 * bb1 + BETA_ * (1.f - ro1) * spk1;
        mem1 = mem1 * alpha1 - bb1 * spk1 + (1.f - alpha1) * s11;
        spk1 = (mem1 - bb1 - BJ0 > 0.f) ? 1.f : 0.f;
        unsigned m1 = __ballot_sync(0xffffffffu, spk1 > 0.5f);

        if (c == 0) { stage[b] = m1; stage[8 + b] = m2prev; }
        __syncthreads();

        // prefetch next step's input projection while exchange is in flight
        const int tn = (t + 1 < T_) ? (t + 1) : (T_ - 1);
        const float i1n = I1row[tn * H1N + j];

        if (b == 0 && c < 8) {
            const uint4* st4 = (const uint4*)stage;
            #pragma unroll
            for (int i = 0; i < 4; i++) {
                uint4 v = st4[i];
                uint32_t la = mba + (par * 128 + rank * 16 + i * 4) * 4;
                ST_CLUSTER_V4(la, (uint32_t)c, v);
            }
            MBAR_ARRIVE_CLUSTER(bar, (uint32_t)c);
        }
        MBAR_WAIT_PARITY_CLUSTER(bar, par);

        const uint32_t* mb = mbw + par * 128;

        // ---- build L2_{t-1} list, then L1_t list (ascending neuron index)
        int n2 = 0;
        #pragma unroll
        for (int m = 0; m < 8; m++) {
            unsigned w = mb[m * 16 + 8 + b];
            if (w & (1u << c))
                L2b[n2 + __popc(w & ((1u << c) - 1u))] = (uint8_t)(m * 32 + c);
            n2 += __popc(w);
        }
        int n1 = 0;
        #pragma unroll
        for (int m = 0; m < 8; m++) {
            unsigned w = mb[m * 16 + b];
            if (w & (1u << c))
                L1b[n1 + __popc(w & ((1u << c) - 1u))] = (uint8_t)(m * 32 + c);
            n1 += __popc(w);
        }
        __syncwarp();

        // ---- pair gather over L1_t (4 split accumulators per output)
        float a1p0 = 0.f, a1p1 = 0.f, a1p2 = 0.f, a1p3 = 0.f;
        float a2p0 = 0.f, a2p1 = 0.f, a2p2 = 0.f, a2p3 = 0.f;
        {
            int i = 0;
            for (; i + 4 <= n1; i += 4) {
                unsigned kk = *(const unsigned*)(L1b + i);
                float2 w0 = wpair_s[(kk & 255u) * 32 + c];
                float2 w1 = wpair_s[((kk >> 8) & 255u) * 32 + c];
                float2 w2 = wpair_s[((kk >> 16) & 255u) * 32 + c];
                float2 w3 = wpair_s[(kk >> 24) * 32 + c];
                a1p0 += w0.x; a2p0 += w0.y;
                a1p1 += w1.x; a2p1 += w1.y;
                a1p2 += w2.x; a2p2 += w2.y;
                a1p3 += w3.x; a2p3 += w3.y;
            }
            for (; i < n1; i++) {
                float2 w = wpair_s[L1b[i] * 32 + c];
                a1p0 += w.x; a2p0 += w.y;
            }
        }
        float a1 = (i1n + bh1) + ((a1p0 + a1p1) + (a1p2 + a1p3));
        float a2 = bh2 + ((a2p0 + a2p1) + (a2p2 + a2p3));

        // ---- w22 gather over L2_{t-1} (4 split accumulators)
        float a3p0 = 0.f, a3p1 = 0.f, a3p2 = 0.f, a3p3 = 0.f;
        {
            int i = 0;
            for (; i + 4 <= n2; i += 4) {
                unsigned kk = *(const unsigned*)(L2b + i);
                a3p0 += w22_s[(kk & 255u) * 32 + c];
                a3p1 += w22_s[((kk >> 8) & 255u) * 32 + c];
                a3p2 += w22_s[((kk >> 16) & 255u) * 32 + c];
                a3p3 += w22_s[(kk >> 24) * 32 + c];
            }
            for (; i < n2; i++) a3p0 += w22_s[L2b[i] * 32 + c];
        }
        float a3 = (a3p0 + a3p1) + (a3p2 + a3p3);

        // ---- layer 2 LIF (step t)
        float h2 = a2 + a3;
        bb2  = ro2 * bb2 + BETA_ * (1.f - ro2) * spk2;
        mem2 = mem2 * alpha2 - bb2 * spk2 + (1.f - alpha2) * h2;
        spk2 = (mem2 - bb2 - BJ0 > 0.f) ? 1.f : 0.f;
        m2prev = __ballot_sync(0xffffffffu, spk2 > 0.5f);

        // store this step's layer-2 mask (output path handled by K3)
        if (c == 0) m2out[t * 8] = m2prev;

        s11 = a1;
    }
    CLUSTER_SYNC_();
}

// ---------------------------------------------------------------------------
// K3a: output drives oin[b,t,:] for all 64000 samples in parallel.
// One warp per (b,t): list-build from masks, gather w_h2o rows (L2-resident).
// ---------------------------------------------------------------------------
__global__ __launch_bounds__(256) void out_gather_kernel(const float* __restrict__ b_og) {
    __shared__ uint8_t lists[8][256];
    const int w = threadIdx.x >> 5;
    const int c = threadIdx.x & 31;
    const int s = blockIdx.x * 8 + w;          // sample = gb*T + t
    if (s >= B_ * T_) return;

    const uint32_t* mw = g_m2 + (size_t)s * 8;
    int n2 = 0;
    #pragma unroll
    for (int m = 0; m < 8; m++) {
        unsigned wv = mw[m];
        if (wv & (1u << c))
            lists[w][n2 + __popc(wv & ((1u << c) - 1u))] = (uint8_t)(m * 32 + c);
        n2 += __popc(wv);
    }
    __syncwarp();

    if (c < DOUT) {
        const uint8_t* lst = lists[w];
        float p0 = 0.f, p1 = 0.f, p2 = 0.f, p3 = 0.f;
        int i = 0;
        for (; i + 4 <= n2; i += 4) {
            unsigned kk = *(const unsigned*)(lst + i);
            p0 += g_Wt_h2o[(kk & 255u) * DOUT + c];
            p1 += g_Wt_h2o[((kk >> 8) & 255u) * DOUT + c];
            p2 += g_Wt_h2o[((kk >> 16) & 255u) * DOUT + c];
            p3 += g_Wt_h2o[(kk >> 24) * DOUT + c];
        }
        for (; i < n2; i++) p0 += g_Wt_h2o[lst[i] * DOUT + c];
        g_oin[(size_t)s * DOUT + c] = b_og[c] + ((p0 + p1) + (p2 + p3));
    }
}

// ---------------------------------------------------------------------------
// K3b: per-batch mem_o scan + softmax accumulation. One warp per batch.
// ---------------------------------------------------------------------------
__global__ __launch_bounds__(256) void out_scan_kernel(const float* __restrict__ tau_m_o,
                                                       float* __restrict__ out) {
    const int b = blockIdx.x * 8 + (threadIdx.x >> 5);
    const int c = threadIdx.x & 31;
    if (b >= B_) return;

    float alpha_o = (c < DOUT) ? expf(-1.f / tau_m_o[c]) : 0.f;
    float mem_o = 0.f, acc_o = 0.f;
    const float* oin_row = g_oin + (size_t)b * T_ * DOUT;

    for (int t = 0; t < T_; t++) {
        float oin = (c < DOUT) ? oin_row[t * DOUT + c] : 0.f;
        mem_o = mem_o * alpha_o + (1.f - alpha_o) * oin;
        float vv = (c < DOUT) ? mem_o : -1e30f;
        float mx = vv;
        #pragma unroll
        for (int s = 16; s > 0; s >>= 1)
            mx = fmaxf(mx, __shfl_xor_sync(0xffffffffu, mx, s));
        float e = (c < DOUT) ? expf(vv - mx) : 0.f;
        float sm = e;
        #pragma unroll
        for (int s = 16; s > 0; s >>= 1)
            sm += __shfl_xor_sync(0xffffffffu, sm, s);
        if (c < DOUT) acc_o += e / sm;
    }
    if (c < DOUT) out[b * DOUT + c] = acc_o;
}

// ---------------------------------------------------------------------------
extern "C" void kernel_launch(void* const* d_in, const int* in_sizes, int n_in,
                              void* d_out, int out_size) {
    const float* x          = (const float*)d_in[0];
    const float* w_i2h1     = (const float*)d_in[1];
    const float* w_h12h1    = (const float*)d_in[2];
    const float* w_h12h2    = (const float*)d_in[3];
    const float* w_h22h2    = (const float*)d_in[4];
    const float* w_h2o      = (const float*)d_in[5];
    const float* b_h1       = (const float*)d_in[6];
    const float* b_h2       = (const float*)d_in[7];
    const float* b_o        = (const float*)d_in[8];
    const float* tau_adp_h1 = (const float*)d_in[9];
    const float* tau_adp_h2 = (const float*)d_in[10];
    const float* tau_m_h1   = (const float*)d_in[11];
    const float* tau_m_h2   = (const float*)d_in[12];
    const float* tau_m_o    = (const float*)d_in[13];

    cudaFuncSetAttribute(input_proj_kernel,
                         cudaFuncAttributeMaxDynamicSharedMemorySize, DIN * 32 * 4);
    cudaFuncSetAttribute(recurrent_kernel,
                         cudaFuncAttributeMaxDynamicSharedMemorySize, SM_TOT);

    prep_kernel<<<(H1N * DIN + 255) / 256, 256>>>(w_i2h1, w_h12h1, w_h12h2,
                                                  w_h22h2, w_h2o);
    xlist_kernel<<<(B_ * T_) / 8, 256>>>(x);
    input_proj_kernel<<<dim3(8, 100), 256, DIN * 32 * 4>>>();
    recurrent_kernel<<<B_, 256, SM_TOT>>>(b_h1, b_h2,
                                          tau_adp_h1, tau_adp_h2,
                                          tau_m_h1, tau_m_h2);
    out_gather_kernel<<<(B_ * T_ + 7) / 8, 256>>>(b_o);
    out_scan_kernel<<<(B_ + 7) / 8, 256>>>(tau_m_o, (float*)d_out);
}

// round 11
// speedup vs baseline: 1.4833x; 1.1395x over previous
#include <cuda_runtime.h>
#include <cstdint>

#define B_    256
#define T_    250
#define DIN   700
#define H1N   256
#define H2N   256
#define DOUT  20
#define BJ0   0.01f
#define BETA_ 1.8f
#define XPAD  704

// ---------------- device globals (no allocations allowed) ------------------
__device__ float          g_I1[B_ * T_ * H1N];      // x @ w_i2h1.T
__device__ float          g_Wt_i2h1[DIN * H1N];     // [d][j]
__device__ float2         g_Wpair[H1N * H1N];       // [k][j] = (w11, w12)
__device__ float          g_Wt22[H2N * H2N];        // [k][j]
__device__ float          g_Wt_h2o[H2N * DOUT];     // [k][o]
__device__ unsigned short g_xlist[B_ * T_ * XPAD];
__device__ int            g_xcnt[B_ * T_];
__device__ uint32_t       g_m2[B_ * T_ * 8];        // layer-2 spike masks

// ---------------- PTX helpers ----------------------------------------------
__device__ __forceinline__ uint32_t smem_u32(const void* p) {
    uint32_t a;
    asm("{ .reg .u64 t; cvta.to.shared.u64 t, %1; cvt.u32.u64 %0, t; }"
        : "=r"(a) : "l"(p));
    return a;
}
__device__ __forceinline__ uint32_t ctarank() {
    uint32_t r; asm("mov.u32 %0, %%cluster_ctarank;" : "=r"(r)); return r;
}
#define MBAR_INIT(addr, cnt) \
    asm volatile("mbarrier.init.shared.b64 [%0], %1;" :: "r"(addr), "r"(cnt) : "memory")
#define ST_CLUSTER_V4(laddr, rnk, v) \
    asm volatile("{ .reg .b32 ra; mapa.shared::cluster.u32 ra, %0, %1; " \
                 "st.shared::cluster.v4.b32 [ra], {%2,%3,%4,%5}; }" \
                 :: "r"(laddr), "r"(rnk), "r"(v.x), "r"(v.y), "r"(v.z), "r"(v.w) \
                 : "memory")
#define MBAR_ARRIVE_CLUSTER(laddr, rnk) \
    asm volatile("{ .reg .b32 ra; mapa.shared::cluster.u32 ra, %0, %1; " \
                 "mbarrier.arrive.release.cluster.shared::cluster.b64 _, [ra]; }" \
                 :: "r"(laddr), "r"(rnk) : "memory")
#define MBAR_WAIT_PARITY_CLUSTER(laddr, ph) do {                               \
    uint32_t _done = 0;                                                        \
    while (!_done) {                                                           \
        asm volatile("{ .reg .pred p; "                                        \
            "mbarrier.try_wait.parity.acquire.cluster.shared::cta.b64 p, [%1], %2, 0x989680; " \
            "selp.b32 %0, 1, 0, p; }"                                          \
            : "=r"(_done) : "r"(laddr), "r"(ph) : "memory");                   \
    }                                                                          \
} while (0)
#define CLUSTER_SYNC_() do {                                                   \
    asm volatile("barrier.cluster.arrive.aligned;" ::: "memory");              \
    asm volatile("barrier.cluster.wait.aligned;" ::: "memory");                \
} while (0)

// ---------------------------------------------------------------------------
// K0: weight transposes / interleaving
// ---------------------------------------------------------------------------
__global__ void prep_kernel(const float* __restrict__ wi,
                            const float* __restrict__ w11,
                            const float* __restrict__ w12,
                            const float* __restrict__ w22,
                            const float* __restrict__ wo) {
    int idx = blockIdx.x * blockDim.x + threadIdx.x;
    if (idx < H1N * DIN) {
        int r = idx / DIN, c = idx % DIN;
        g_Wt_i2h1[c * H1N + r] = wi[idx];
    }
    if (idx < H1N * H1N) {
        int r = idx / H1N, c = idx % H1N;
        g_Wpair[c * H1N + r] = make_float2(w11[idx], w12[idx]);
        g_Wt22[c * H1N + r]  = w22[idx];
    }
    if (idx < DOUT * H2N) {
        int r = idx / H2N, c = idx % H2N;
        g_Wt_h2o[c * DOUT + r] = wo[idx];
    }
}

// ---------------------------------------------------------------------------
// K0b: per-sample active-input lists (ascending d), one warp per sample
// ---------------------------------------------------------------------------
__global__ __launch_bounds__(256) void xlist_kernel(const float* __restrict__ x) {
    int s    = blockIdx.x * 8 + (threadIdx.x >> 5);
    int lane = threadIdx.x & 31;
    if (s >= B_ * T_) return;
    const float* xr = x + (size_t)s * DIN;
    int cnt = 0;
    for (int base = 0; base < DIN; base += 32) {
        int d = base + lane;
        float v = (d < DIN) ? xr[d] : 0.f;
        unsigned m = __ballot_sync(0xffffffffu, v != 0.f);
        if (v != 0.f)
            g_xlist[(size_t)s * XPAD + cnt + __popc(m & ((1u << lane) - 1u))] =
                (unsigned short)d;
        cnt += __popc(m);
    }
    if (lane == 0) g_xcnt[s] = cnt;
}

// ---------------------------------------------------------------------------
// K1: input projection, col-split smem weight tile. Counts preloaded to smem;
// TWO samples interleaved per warp (independent accumulators/lists double the
// memory-level parallelism on the serial per-sample chain). Per-sample
// accumulation order identical to R10 (4-way split, ascending d).
// ---------------------------------------------------------------------------
#define K1_WT_BYTES  (DIN * 32 * 4)                   // 89600
#define K1_SMEM      (K1_WT_BYTES + 640 * 4)          // + counts

__global__ __launch_bounds__(256, 2) void input_proj_kernel() {
    extern __shared__ float wt[];                     // [700][32]
    int* cnt_s = (int*)((char*)wt + K1_WT_BYTES);     // [640]
    const int ct   = blockIdx.x;
    const int grp  = blockIdx.y;
    const int tid  = threadIdx.x;
    const int warp = tid >> 5;
    const int lane = tid & 31;

    for (int idx = tid; idx < DIN * 32; idx += 256) {
        int d = idx >> 5, c = idx & 31;
        wt[idx] = g_Wt_i2h1[d * H1N + ct * 32 + c];
    }
    for (int idx = tid; idx < 640; idx += 256)
        cnt_s[idx] = g_xcnt[grp * 640 + idx];
    __syncthreads();

    const int base = grp * 640 + warp * 80;
    for (int sp = 0; sp < 80; sp += 2) {
        const int s0 = base + sp, s1 = s0 + 1;
        const int n0 = cnt_s[warp * 80 + sp];
        const int n1 = cnt_s[warp * 80 + sp + 1];
        const unsigned short* l0 = g_xlist + (size_t)s0 * XPAD;
        const unsigned short* l1 = g_xlist + (size_t)s1 * XPAD;

        float a0 = 0.f, a1 = 0.f, a2 = 0.f, a3 = 0.f;
        float b0 = 0.f, b1 = 0.f, b2 = 0.f, b3 = 0.f;

        const int m = (n0 < n1 ? n0 : n1) & ~3;
        int i = 0;
        for (; i < m; i += 4) {
            ushort4 ka = *(const ushort4*)(l0 + i);
            ushort4 kb = *(const ushort4*)(l1 + i);
            a0 += wt[ka.x * 32 + lane];
            b0 += wt[kb.x * 32 + lane];
            a1 += wt[ka.y * 32 + lane];
            b1 += wt[kb.y * 32 + lane];
            a2 += wt[ka.z * 32 + lane];
            b2 += wt[kb.z * 32 + lane];
            a3 += wt[ka.w * 32 + lane];
            b3 += wt[kb.w * 32 + lane];
        }
        int ia = i;
        for (; ia + 4 <= n0; ia += 4) {
            ushort4 ka = *(const ushort4*)(l0 + ia);
            a0 += wt[ka.x * 32 + lane];
            a1 += wt[ka.y * 32 + lane];
            a2 += wt[ka.z * 32 + lane];
            a3 += wt[ka.w * 32 + lane];
        }
        for (; ia < n0; ia++) a0 += wt[l0[ia] * 32 + lane];
        int ib = i;
        for (; ib + 4 <= n1; ib += 4) {
            ushort4 kb = *(const ushort4*)(l1 + ib);
            b0 += wt[kb.x * 32 + lane];
            b1 += wt[kb.y * 32 + lane];
            b2 += wt[kb.z * 32 + lane];
            b3 += wt[kb.w * 32 + lane];
        }
        for (; ib < n1; ib++) b0 += wt[l1[ib] * 32 + lane];

        g_I1[(size_t)s0 * H1N + ct * 32 + lane] = (a0 + a1) + (a2 + a3);
        g_I1[(size_t)s1 * H1N + ct * 32 + lane] = (b0 + b1) + (b2 + b3);
    }
}

// ---------------------------------------------------------------------------
// K2: cluster-cooperative recurrent kernel (R10 structure — at smem BW floor).
// ---------------------------------------------------------------------------
#define SM_WPAIR 0
#define SM_W22   65536
#define SM_L1    98304               // 8 * 256 bytes
#define SM_L2    100352              // 8 * 256 bytes
#define SM_STAGE 102400              // 16 u32 (16B aligned)
#define SM_MB    102464              // 2*8*16 u32 = 1024 B
#define SM_BAR   103488
#define SM_TOT   103504

__global__ __launch_bounds__(256, 2) __cluster_dims__(8, 1, 1)
void recurrent_kernel(
    const float* __restrict__ b_h1g, const float* __restrict__ b_h2g,
    const float* __restrict__ tau_adp_h1, const float* __restrict__ tau_adp_h2,
    const float* __restrict__ tau_m_h1,  const float* __restrict__ tau_m_h2) {

    extern __shared__ __align__(16) char smraw[];
    float2*         wpair_s = (float2*)(smraw + SM_WPAIR);   // [k*32+c]
    float*          w22_s   = (float*)(smraw + SM_W22);      // [k*32+c]
    uint8_t*        L1s     = (uint8_t*)(smraw + SM_L1);     // [b][256]
    uint8_t*        L2s     = (uint8_t*)(smraw + SM_L2);
    uint32_t*       stage   = (uint32_t*)(smraw + SM_STAGE); // [16]
    const uint32_t* mbw     = (const uint32_t*)(smraw + SM_MB);
    const uint32_t  smb     = smem_u32(smraw);
    const uint32_t  bar     = smb + SM_BAR;
    const uint32_t  mba     = smb + SM_MB;

    const int tid  = threadIdx.x;
    const int b    = tid >> 5;                 // warp = local batch
    const int c    = tid & 31;                 // lane = local column
    const uint32_t rank = ctarank();
    const int j    = rank * 32 + c;            // owned neuron
    const int gb   = (blockIdx.x >> 3) * 8 + b;

    for (int idx = tid; idx < H1N * 32; idx += 256) {
        int k = idx >> 5, cc = idx & 31;
        wpair_s[idx] = g_Wpair[k * H1N + rank * 32 + cc];
        w22_s[idx]   = g_Wt22[k * H1N + rank * 32 + cc];
    }
    if (tid == 0) MBAR_INIT(bar, 8);
    __syncthreads();
    CLUSTER_SYNC_();

    const float alpha1 = expf(-1.f / tau_m_h1[j]);
    const float ro1    = expf(-1.f / tau_adp_h1[j]);
    const float alpha2 = expf(-1.f / tau_m_h2[j]);
    const float ro2    = expf(-1.f / tau_adp_h2[j]);
    const float bh1    = b_h1g[j];
    const float bh2    = b_h2g[j];

    float mem1 = 0.f, spk1 = 0.f, bb1 = BJ0;
    float mem2 = 0.f, spk2 = 0.f, bb2 = BJ0;
    unsigned m2prev = 0u;

    const float* I1row = g_I1 + (size_t)gb * T_ * H1N;
    float s11 = I1row[j] + bh1;                // t=0: no recurrent terms

    uint8_t* L1b = L1s + b * 256;
    uint8_t* L2b = L2s + b * 256;
    uint32_t* m2out = g_m2 + (size_t)gb * T_ * 8 + rank;

    for (int t = 0; t < T_; t++) {
        const int par = t & 1;

        bb1  = ro1 * bb1 + BETA_ * (1.f - ro1) * spk1;
        mem1 = mem1 * alpha1 - bb1 * spk1 + (1.f - alpha1) * s11;
        spk1 = (mem1 - bb1 - BJ0 > 0.f) ? 1.f : 0.f;
        unsigned m1 = __ballot_sync(0xffffffffu, spk1 > 0.5f);

        if (c == 0) { stage[b] = m1; stage[8 + b] = m2prev; }
        __syncthreads();

        const int tn = (t + 1 < T_) ? (t + 1) : (T_ - 1);
        const float i1n = I1row[tn * H1N + j];

        if (b == 0 && c < 8) {
            const uint4* st4 = (const uint4*)stage;
            #pragma unroll
            for (int i = 0; i < 4; i++) {
                uint4 v = st4[i];
                uint32_t la = mba + (par * 128 + rank * 16 + i * 4) * 4;
                ST_CLUSTER_V4(la, (uint32_t)c, v);
            }
            MBAR_ARRIVE_CLUSTER(bar, (uint32_t)c);
        }
        MBAR_WAIT_PARITY_CLUSTER(bar, par);

        const uint32_t* mb = mbw + par * 128;

        int n2 = 0;
        #pragma unroll
        for (int m = 0; m < 8; m++) {
            unsigned w = mb[m * 16 + 8 + b];
            if (w & (1u << c))
                L2b[n2 + __popc(w & ((1u << c) - 1u))] = (uint8_t)(m * 32 + c);
            n2 += __popc(w);
        }
        int n1 = 0;
        #pragma unroll
        for (int m = 0; m < 8; m++) {
            unsigned w = mb[m * 16 + b];
            if (w & (1u << c))
                L1b[n1 + __popc(w & ((1u << c) - 1u))] = (uint8_t)(m * 32 + c);
            n1 += __popc(w);
        }
        __syncwarp();

        float a1p0 = 0.f, a1p1 = 0.f, a1p2 = 0.f, a1p3 = 0.f;
        float a2p0 = 0.f, a2p1 = 0.f, a2p2 = 0.f, a2p3 = 0.f;
        {
            int i = 0;
            for (; i + 4 <= n1; i += 4) {
                unsigned kk = *(const unsigned*)(L1b + i);
                float2 w0 = wpair_s[(kk & 255u) * 32 + c];
                float2 w1 = wpair_s[((kk >> 8) & 255u) * 32 + c];
                float2 w2 = wpair_s[((kk >> 16) & 255u) * 32 + c];
                float2 w3 = wpair_s[(kk >> 24) * 32 + c];
                a1p0 += w0.x; a2p0 += w0.y;
                a1p1 += w1.x; a2p1 += w1.y;
                a1p2 += w2.x; a2p2 += w2.y;
                a1p3 += w3.x; a2p3 += w3.y;
            }
            for (; i < n1; i++) {
                float2 w = wpair_s[L1b[i] * 32 + c];
                a1p0 += w.x; a2p0 += w.y;
            }
        }
        float a1 = (i1n + bh1) + ((a1p0 + a1p1) + (a1p2 + a1p3));
        float a2 = bh2 + ((a2p0 + a2p1) + (a2p2 + a2p3));

        float a3p0 = 0.f, a3p1 = 0.f, a3p2 = 0.f, a3p3 = 0.f;
        {
            int i = 0;
            for (; i + 4 <= n2; i += 4) {
                unsigned kk = *(const unsigned*)(L2b + i);
                a3p0 += w22_s[(kk & 255u) * 32 + c];
                a3p1 += w22_s[((kk >> 8) & 255u) * 32 + c];
                a3p2 += w22_s[((kk >> 16) & 255u) * 32 + c];
                a3p3 += w22_s[(kk >> 24) * 32 + c];
            }
            for (; i < n2; i++) a3p0 += w22_s[L2b[i] * 32 + c];
        }
        float a3 = (a3p0 + a3p1) + (a3p2 + a3p3);

        float h2 = a2 + a3;
        bb2  = ro2 * bb2 + BETA_ * (1.f - ro2) * spk2;
        mem2 = mem2 * alpha2 - bb2 * spk2 + (1.f - alpha2) * h2;
        spk2 = (mem2 - bb2 - BJ0 > 0.f) ? 1.f : 0.f;
        m2prev = __ballot_sync(0xffffffffu, spk2 > 0.5f);

        if (c == 0) m2out[t * 8] = m2prev;

        s11 = a1;
    }
    CLUSTER_SYNC_();
}

// ---------------------------------------------------------------------------
// K3 (fused): CTA = batch. 8 warps compute oin[t,:] into smem (t strided by
// warp), then warp 0 runs the serial mem_o scan + softmax accumulation.
// Same arithmetic/order as R10's K3a+K3b (no global oin roundtrip).
// ---------------------------------------------------------------------------
__global__ __launch_bounds__(256) void out_kernel(const float* __restrict__ b_og,
                                                  const float* __restrict__ tau_m_o,
                                                  float* __restrict__ out) {
    __shared__ float   oin_s[T_ * DOUT];        // 20 KB
    __shared__ uint8_t lists[8][256];

    const int bidx = blockIdx.x;
    const int w    = threadIdx.x >> 5;
    const int c    = threadIdx.x & 31;
    const float bo = (c < DOUT) ? b_og[c] : 0.f;

    const uint32_t* mbase = g_m2 + (size_t)bidx * T_ * 8;
    for (int t = w; t < T_; t += 8) {
        const uint32_t* mw = mbase + t * 8;
        int n2 = 0;
        #pragma unroll
        for (int m = 0; m < 8; m++) {
            unsigned wv = mw[m];
            if (wv & (1u << c))
                lists[w][n2 + __popc(wv & ((1u << c) - 1u))] = (uint8_t)(m * 32 + c);
            n2 += __popc(wv);
        }
        __syncwarp();
        if (c < DOUT) {
            const uint8_t* lst = lists[w];
            float p0 = 0.f, p1 = 0.f, p2 = 0.f, p3 = 0.f;
            int i = 0;
            for (; i + 4 <= n2; i += 4) {
                unsigned kk = *(const unsigned*)(lst + i);
                p0 += g_Wt_h2o[(kk & 255u) * DOUT + c];
                p1 += g_Wt_h2o[((kk >> 8) & 255u) * DOUT + c];
                p2 += g_Wt_h2o[((kk >> 16) & 255u) * DOUT + c];
                p3 += g_Wt_h2o[(kk >> 24) * DOUT + c];
            }
            for (; i < n2; i++) p0 += g_Wt_h2o[lst[i] * DOUT + c];
            oin_s[t * DOUT + c] = bo + ((p0 + p1) + (p2 + p3));
        }
        __syncwarp();
    }
    __syncthreads();

    if (w == 0) {
        float alpha_o = (c < DOUT) ? expf(-1.f / tau_m_o[c]) : 0.f;
        float mem_o = 0.f, acc_o = 0.f;
        for (int t = 0; t < T_; t++) {
            float oin = (c < DOUT) ? oin_s[t * DOUT + c] : 0.f;
            mem_o = mem_o * alpha_o + (1.f - alpha_o) * oin;
            float vv = (c < DOUT) ? mem_o : -1e30f;
            float mx = vv;
            #pragma unroll
            for (int s = 16; s > 0; s >>= 1)
                mx = fmaxf(mx, __shfl_xor_sync(0xffffffffu, mx, s));
            float e = (c < DOUT) ? expf(vv - mx) : 0.f;
            float sm = e;
            #pragma unroll
            for (int s = 16; s > 0; s >>= 1)
                sm += __shfl_xor_sync(0xffffffffu, sm, s);
            if (c < DOUT) acc_o += e / sm;
        }
        if (c < DOUT) out[bidx * DOUT + c] = acc_o;
    }
}

// ---------------------------------------------------------------------------
extern "C" void kernel_launch(void* const* d_in, const int* in_sizes, int n_in,
                              void* d_out, int out_size) {
    const float* x          = (const float*)d_in[0];
    const float* w_i2h1     = (const float*)d_in[1];
    const float* w_h12h1    = (const float*)d_in[2];
    const float* w_h12h2    = (const float*)d_in[3];
    const float* w_h22h2    = (const float*)d_in[4];
    const float* w_h2o      = (const float*)d_in[5];
    const float* b_h1       = (const float*)d_in[6];
    const float* b_h2       = (const float*)d_in[7];
    const float* b_o        = (const float*)d_in[8];
    const float* tau_adp_h1 = (const float*)d_in[9];
    const float* tau_adp_h2 = (const float*)d_in[10];
    const float* tau_m_h1   = (const float*)d_in[11];
    const float* tau_m_h2   = (const float*)d_in[12];
    const float* tau_m_o    = (const float*)d_in[13];

    cudaFuncSetAttribute(input_proj_kernel,
                         cudaFuncAttributeMaxDynamicSharedMemorySize, K1_SMEM);
    cudaFuncSetAttribute(recurrent_kernel,
                         cudaFuncAttributeMaxDynamicSharedMemorySize, SM_TOT);

    prep_kernel<<<(H1N * DIN + 255) / 256, 256>>>(w_i2h1, w_h12h1, w_h12h2,
                                                  w_h22h2, w_h2o);
    xlist_kernel<<<(B_ * T_) / 8, 256>>>(x);
    input_proj_kernel<<<dim3(8, 100), 256, K1_SMEM>>>();
    recurrent_kernel<<<B_, 256, SM_TOT>>>(b_h1, b_h2,
                                          tau_adp_h1, tau_adp_h2,
                                          tau_m_h1, tau_m_h2);
    out_kernel<<<B_, 256>>>(b_o, tau_m_o, (float*)d_out);
}

// round 12
// speedup vs baseline: 1.4834x; 1.0001x over previous
#include <cuda_runtime.h>
#include <cstdint>

#define B_    256
#define T_    250
#define DIN   700
#define H1N   256
#define H2N   256
#define DOUT  20
#define BJ0   0.01f
#define BETA_ 1.8f
#define XPAD  704

// ---------------- device globals (no allocations allowed) ------------------
__device__ float          g_I1[B_ * T_ * H1N];      // x @ w_i2h1.T
__device__ float          g_Wt_i2h1[DIN * H1N];     // [d][j]
__device__ float2         g_Wpair[H1N * H1N];       // [k][j] = (w11, w12)
__device__ float          g_Wt22[H2N * H2N];        // [k][j]
__device__ float          g_Wt_h2o[H2N * DOUT];     // [k][o]
__device__ unsigned short g_xlist[B_ * T_ * XPAD];
__device__ int            g_xcnt[B_ * T_];
__device__ uint32_t       g_m2[B_ * T_ * 8];        // layer-2 spike masks

// ---------------- PTX helpers ----------------------------------------------
__device__ __forceinline__ uint32_t smem_u32(const void* p) {
    uint32_t a;
    asm("{ .reg .u64 t; cvta.to.shared.u64 t, %1; cvt.u32.u64 %0, t; }"
        : "=r"(a) : "l"(p));
    return a;
}
__device__ __forceinline__ uint32_t ctarank() {
    uint32_t r; asm("mov.u32 %0, %%cluster_ctarank;" : "=r"(r)); return r;
}
#define MBAR_INIT(addr, cnt) \
    asm volatile("mbarrier.init.shared.b64 [%0], %1;" :: "r"(addr), "r"(cnt) : "memory")
#define ST_CLUSTER_V4(laddr, rnk, v) \
    asm volatile("{ .reg .b32 ra; mapa.shared::cluster.u32 ra, %0, %1; " \
                 "st.shared::cluster.v4.b32 [ra], {%2,%3,%4,%5}; }" \
                 :: "r"(laddr), "r"(rnk), "r"(v.x), "r"(v.y), "r"(v.z), "r"(v.w) \
                 : "memory")
#define MBAR_ARRIVE_CLUSTER(laddr, rnk) \
    asm volatile("{ .reg .b32 ra; mapa.shared::cluster.u32 ra, %0, %1; " \
                 "mbarrier.arrive.release.cluster.shared::cluster.b64 _, [ra]; }" \
                 :: "r"(laddr), "r"(rnk) : "memory")
#define MBAR_WAIT_PARITY_CLUSTER(laddr, ph) do {                               \
    uint32_t _done = 0;                                                        \
    while (!_done) {                                                           \
        asm volatile("{ .reg .pred p; "                                        \
            "mbarrier.try_wait.parity.acquire.cluster.shared::cta.b64 p, [%1], %2, 0x989680; " \
            "selp.b32 %0, 1, 0, p; }"                                          \
            : "=r"(_done) : "r"(laddr), "r"(ph) : "memory");                   \
    }                                                                          \
} while (0)
#define CLUSTER_SYNC_() do {                                                   \
    asm volatile("barrier.cluster.arrive.aligned;" ::: "memory");              \
    asm volatile("barrier.cluster.wait.aligned;" ::: "memory");                \
} while (0)

// ---------------------------------------------------------------------------
// K0: weight transposes / interleaving
// ---------------------------------------------------------------------------
__global__ void prep_kernel(const float* __restrict__ wi,
                            const float* __restrict__ w11,
                            const float* __restrict__ w12,
                            const float* __restrict__ w22,
                            const float* __restrict__ wo) {
    int idx = blockIdx.x * blockDim.x + threadIdx.x;
    if (idx < H1N * DIN) {
        int r = idx / DIN, c = idx % DIN;
        g_Wt_i2h1[c * H1N + r] = wi[idx];
    }
    if (idx < H1N * H1N) {
        int r = idx / H1N, c = idx % H1N;
        g_Wpair[c * H1N + r] = make_float2(w11[idx], w12[idx]);
        g_Wt22[c * H1N + r]  = w22[idx];
    }
    if (idx < DOUT * H2N) {
        int r = idx / H2N, c = idx % H2N;
        g_Wt_h2o[c * DOUT + r] = wo[idx];
    }
}

// ---------------------------------------------------------------------------
// K0b: per-sample active-input lists (ascending d), one warp per sample
// ---------------------------------------------------------------------------
__global__ __launch_bounds__(256) void xlist_kernel(const float* __restrict__ x) {
    int s    = blockIdx.x * 8 + (threadIdx.x >> 5);
    int lane = threadIdx.x & 31;
    if (s >= B_ * T_) return;
    const float* xr = x + (size_t)s * DIN;
    int cnt = 0;
    for (int base = 0; base < DIN; base += 32) {
        int d = base + lane;
        float v = (d < DIN) ? xr[d] : 0.f;
        unsigned m = __ballot_sync(0xffffffffu, v != 0.f);
        if (v != 0.f)
            g_xlist[(size_t)s * XPAD + cnt + __popc(m & ((1u << lane) - 1u))] =
                (unsigned short)d;
        cnt += __popc(m);
    }
    if (lane == 0) g_xcnt[s] = cnt;
}

// ---------------------------------------------------------------------------
// K1: input projection. Two samples interleaved per warp, 1-deep index-block
// prefetch in the shared min-block. Per-sample accumulation order identical
// to R11 (4-way split, ascending d).
// ---------------------------------------------------------------------------
#define K1_WT_BYTES  (DIN * 32 * 4)                   // 89600
#define K1_SMEM      (K1_WT_BYTES + 640 * 4)          // + counts

__global__ __launch_bounds__(256, 2) void input_proj_kernel() {
    extern __shared__ float wt[];                     // [700][32]
    int* cnt_s = (int*)((char*)wt + K1_WT_BYTES);     // [640]
    const int ct   = blockIdx.x;
    const int grp  = blockIdx.y;
    const int tid  = threadIdx.x;
    const int warp = tid >> 5;
    const int lane = tid & 31;

    for (int idx = tid; idx < DIN * 32; idx += 256) {
        int d = idx >> 5, c = idx & 31;
        wt[idx] = g_Wt_i2h1[d * H1N + ct * 32 + c];
    }
    for (int idx = tid; idx < 640; idx += 256)
        cnt_s[idx] = g_xcnt[grp * 640 + idx];
    __syncthreads();

    const int base = grp * 640 + warp * 80;
    for (int sp = 0; sp < 80; sp += 2) {
        const int s0 = base + sp, s1 = s0 + 1;
        const int n0 = cnt_s[warp * 80 + sp];
        const int n1 = cnt_s[warp * 80 + sp + 1];
        const unsigned short* l0 = g_xlist + (size_t)s0 * XPAD;
        const unsigned short* l1 = g_xlist + (size_t)s1 * XPAD;

        float a0 = 0.f, a1 = 0.f, a2 = 0.f, a3 = 0.f;
        float b0 = 0.f, b1 = 0.f, b2 = 0.f, b3 = 0.f;

        const int m = (n0 < n1 ? n0 : n1) & ~3;
        int i = 0;
        if (m >= 4) {
            ushort4 ka = *(const ushort4*)(l0);
            ushort4 kb = *(const ushort4*)(l1);
            for (; i + 8 <= m; i += 4) {
                ushort4 kan = *(const ushort4*)(l0 + i + 4);
                ushort4 kbn = *(const ushort4*)(l1 + i + 4);
                a0 += wt[ka.x * 32 + lane];
                b0 += wt[kb.x * 32 + lane];
                a1 += wt[ka.y * 32 + lane];
                b1 += wt[kb.y * 32 + lane];
                a2 += wt[ka.z * 32 + lane];
                b2 += wt[kb.z * 32 + lane];
                a3 += wt[ka.w * 32 + lane];
                b3 += wt[kb.w * 32 + lane];
                ka = kan; kb = kbn;
            }
            a0 += wt[ka.x * 32 + lane];
            b0 += wt[kb.x * 32 + lane];
            a1 += wt[ka.y * 32 + lane];
            b1 += wt[kb.y * 32 + lane];
            a2 += wt[ka.z * 32 + lane];
            b2 += wt[kb.z * 32 + lane];
            a3 += wt[ka.w * 32 + lane];
            b3 += wt[kb.w * 32 + lane];
            i += 4;
        }
        int ia = i;
        for (; ia + 4 <= n0; ia += 4) {
            ushort4 ka = *(const ushort4*)(l0 + ia);
            a0 += wt[ka.x * 32 + lane];
            a1 += wt[ka.y * 32 + lane];
            a2 += wt[ka.z * 32 + lane];
            a3 += wt[ka.w * 32 + lane];
        }
        for (; ia < n0; ia++) a0 += wt[l0[ia] * 32 + lane];
        int ib = i;
        for (; ib + 4 <= n1; ib += 4) {
            ushort4 kb = *(const ushort4*)(l1 + ib);
            b0 += wt[kb.x * 32 + lane];
            b1 += wt[kb.y * 32 + lane];
            b2 += wt[kb.z * 32 + lane];
            b3 += wt[kb.w * 32 + lane];
        }
        for (; ib < n1; ib++) b0 += wt[l1[ib] * 32 + lane];

        g_I1[(size_t)s0 * H1N + ct * 32 + lane] = (a0 + a1) + (a2 + a3);
        g_I1[(size_t)s1 * H1N + ct * 32 + lane] = (b0 + b1) + (b2 + b3);
    }
}

// ---------------------------------------------------------------------------
// K2: cluster-cooperative recurrent kernel. Single exchange per step; the
// rank-LOCAL windows of the gathers run between funnel-send and mbarrier
// wait (each warp's own ballots ARE the local mask words), hiding exchange
// latency. Post-wait list builds skip m == rank.
// ---------------------------------------------------------------------------
#define SM_WPAIR 0
#define SM_W22   65536
#define SM_L1    98304               // 8 * 256 bytes
#define SM_L2    100352              // 8 * 256 bytes
#define SM_STAGE 102400              // 16 u32 (16B aligned)
#define SM_MB    102464              // 2*8*16 u32 = 1024 B
#define SM_BAR   103488
#define SM_TOT   103504

__global__ __launch_bounds__(256, 2) __cluster_dims__(8, 1, 1)
void recurrent_kernel(
    const float* __restrict__ b_h1g, const float* __restrict__ b_h2g,
    const float* __restrict__ tau_adp_h1, const float* __restrict__ tau_adp_h2,
    const float* __restrict__ tau_m_h1,  const float* __restrict__ tau_m_h2) {

    extern __shared__ __align__(16) char smraw[];
    float2*         wpair_s = (float2*)(smraw + SM_WPAIR);   // [k*32+c]
    float*          w22_s   = (float*)(smraw + SM_W22);      // [k*32+c]
    uint8_t*        L1s     = (uint8_t*)(smraw + SM_L1);     // [b][256]
    uint8_t*        L2s     = (uint8_t*)(smraw + SM_L2);
    uint32_t*       stage   = (uint32_t*)(smraw + SM_STAGE); // [16]
    const uint32_t* mbw     = (const uint32_t*)(smraw + SM_MB);
    const uint32_t  smb     = smem_u32(smraw);
    const uint32_t  bar     = smb + SM_BAR;
    const uint32_t  mba     = smb + SM_MB;

    const int tid  = threadIdx.x;
    const int b    = tid >> 5;                 // warp = local batch
    const int c    = tid & 31;                 // lane = local column
    const uint32_t rank = ctarank();
    const int j    = rank * 32 + c;            // owned neuron
    const int gb   = (blockIdx.x >> 3) * 8 + b;
    const int kloc = rank * 32;                // local k-window base

    for (int idx = tid; idx < H1N * 32; idx += 256) {
        int k = idx >> 5, cc = idx & 31;
        wpair_s[idx] = g_Wpair[k * H1N + rank * 32 + cc];
        w22_s[idx]   = g_Wt22[k * H1N + rank * 32 + cc];
    }
    if (tid == 0) MBAR_INIT(bar, 8);
    __syncthreads();
    CLUSTER_SYNC_();

    const float alpha1 = expf(-1.f / tau_m_h1[j]);
    const float ro1    = expf(-1.f / tau_adp_h1[j]);
    const float alpha2 = expf(-1.f / tau_m_h2[j]);
    const float ro2    = expf(-1.f / tau_adp_h2[j]);
    const float bh1    = b_h1g[j];
    const float bh2    = b_h2g[j];

    float mem1 = 0.f, spk1 = 0.f, bb1 = BJ0;
    float mem2 = 0.f, spk2 = 0.f, bb2 = BJ0;
    unsigned m2prev = 0u;

    const float* I1row = g_I1 + (size_t)gb * T_ * H1N;
    float s11 = I1row[j] + bh1;                // t=0: no recurrent terms

    uint8_t* L1b = L1s + b * 256;
    uint8_t* L2b = L2s + b * 256;
    uint32_t* m2out = g_m2 + (size_t)gb * T_ * 8 + rank;

    for (int t = 0; t < T_; t++) {
        const int par = t & 1;

        bb1  = ro1 * bb1 + BETA_ * (1.f - ro1) * spk1;
        mem1 = mem1 * alpha1 - bb1 * spk1 + (1.f - alpha1) * s11;
        spk1 = (mem1 - bb1 - BJ0 > 0.f) ? 1.f : 0.f;
        unsigned m1 = __ballot_sync(0xffffffffu, spk1 > 0.5f);

        if (c == 0) { stage[b] = m1; stage[8 + b] = m2prev; }
        __syncthreads();

        const int tn = (t + 1 < T_) ? (t + 1) : (T_ - 1);
        const float i1n = I1row[tn * H1N + j];

        if (b == 0 && c < 8) {
            const uint4* st4 = (const uint4*)stage;
            #pragma unroll
            for (int i = 0; i < 4; i++) {
                uint4 v = st4[i];
                uint32_t la = mba + (par * 128 + rank * 16 + i * 4) * 4;
                ST_CLUSTER_V4(la, (uint32_t)c, v);
            }
            MBAR_ARRIVE_CLUSTER(bar, (uint32_t)c);
        }

        // ---- local-window gathers (own rank) — overlap with the exchange.
        // m1 and m2prev ARE the local mask words for this warp's batch.
        float la1 = 0.f, la2 = 0.f, la3 = 0.f;
        {
            unsigned w = m1;
            while (w) {
                int k = __ffs(w) - 1; w &= w - 1;
                float2 ww = wpair_s[(kloc + k) * 32 + c];
                la1 += ww.x; la2 += ww.y;
            }
            unsigned w2 = m2prev;
            while (w2) {
                int k = __ffs(w2) - 1; w2 &= w2 - 1;
                la3 += w22_s[(kloc + k) * 32 + c];
            }
        }

        MBAR_WAIT_PARITY_CLUSTER(bar, par);

        const uint32_t* mb = mbw + par * 128;

        // ---- build remote-window lists (ascending k, skipping own rank)
        int n2 = 0;
        #pragma unroll
        for (int m = 0; m < 8; m++) {
            if (m == (int)rank) continue;
            unsigned w = mb[m * 16 + 8 + b];
            if (w & (1u << c))
                L2b[n2 + __popc(w & ((1u << c) - 1u))] = (uint8_t)(m * 32 + c);
            n2 += __popc(w);
        }
        int n1 = 0;
        #pragma unroll
        for (int m = 0; m < 8; m++) {
            if (m == (int)rank) continue;
            unsigned w = mb[m * 16 + b];
            if (w & (1u << c))
                L1b[n1 + __popc(w & ((1u << c) - 1u))] = (uint8_t)(m * 32 + c);
            n1 += __popc(w);
        }
        __syncwarp();

        float a1p0 = 0.f, a1p1 = 0.f, a1p2 = 0.f, a1p3 = 0.f;
        float a2p0 = 0.f, a2p1 = 0.f, a2p2 = 0.f, a2p3 = 0.f;
        {
            int i = 0;
            for (; i + 4 <= n1; i += 4) {
                unsigned kk = *(const unsigned*)(L1b + i);
                float2 w0 = wpair_s[(kk & 255u) * 32 + c];
                float2 w1 = wpair_s[((kk >> 8) & 255u) * 32 + c];
                float2 w2 = wpair_s[((kk >> 16) & 255u) * 32 + c];
                float2 w3 = wpair_s[(kk >> 24) * 32 + c];
                a1p0 += w0.x; a2p0 += w0.y;
                a1p1 += w1.x; a2p1 += w1.y;
                a1p2 += w2.x; a2p2 += w2.y;
                a1p3 += w3.x; a2p3 += w3.y;
            }
            for (; i < n1; i++) {
                float2 w = wpair_s[L1b[i] * 32 + c];
                a1p0 += w.x; a2p0 += w.y;
            }
        }
        float a1 = (i1n + bh1) + ((a1p0 + a1p1) + (a1p2 + a1p3)) + la1;
        float a2 = bh2 + ((a2p0 + a2p1) + (a2p2 + a2p3)) + la2;

        float a3p0 = 0.f, a3p1 = 0.f, a3p2 = 0.f, a3p3 = 0.f;
        {
            int i = 0;
            for (; i + 4 <= n2; i += 4) {
                unsigned kk = *(const unsigned*)(L2b + i);
                a3p0 += w22_s[(kk & 255u) * 32 + c];
                a3p1 += w22_s[((kk >> 8) & 255u) * 32 + c];
                a3p2 += w22_s[((kk >> 16) & 255u) * 32 + c];
                a3p3 += w22_s[(kk >> 24) * 32 + c];
            }
            for (; i < n2; i++) a3p0 += w22_s[L2b[i] * 32 + c];
        }
        float a3 = ((a3p0 + a3p1) + (a3p2 + a3p3)) + la3;

        float h2 = a2 + a3;
        bb2  = ro2 * bb2 + BETA_ * (1.f - ro2) * spk2;
        mem2 = mem2 * alpha2 - bb2 * spk2 + (1.f - alpha2) * h2;
        spk2 = (mem2 - bb2 - BJ0 > 0.f) ? 1.f : 0.f;
        m2prev = __ballot_sync(0xffffffffu, spk2 > 0.5f);

        if (c == 0) m2out[t * 8] = m2prev;

        s11 = a1;
    }
    CLUSTER_SYNC_();
}

// ---------------------------------------------------------------------------
// K3 (fused): CTA = batch. Phase A: 8 warps compute oin[t,:] into smem.
// Phase B: warp 0 runs the serial mem_o scan in place (identical arithmetic).
// Phase C: all 8 warps softmax strided timesteps; partials reduced at end.
// ---------------------------------------------------------------------------
__global__ __launch_bounds__(256) void out_kernel(const float* __restrict__ b_og,
                                                  const float* __restrict__ tau_m_o,
                                                  float* __restrict__ out) {
    __shared__ float   oin_s[T_ * DOUT];        // 20 KB (reused for mem_o)
    __shared__ uint8_t lists[8][256];
    __shared__ float   acc_part[8][DOUT];

    const int bidx = blockIdx.x;
    const int w    = threadIdx.x >> 5;
    const int c    = threadIdx.x & 31;
    const float bo = (c < DOUT) ? b_og[c] : 0.f;

    // Phase A: output drives
    const uint32_t* mbase = g_m2 + (size_t)bidx * T_ * 8;
    for (int t = w; t < T_; t += 8) {
        const uint32_t* mw = mbase + t * 8;
        int n2 = 0;
        #pragma unroll
        for (int m = 0; m < 8; m++) {
            unsigned wv = mw[m];
            if (wv & (1u << c))
                lists[w][n2 + __popc(wv & ((1u << c) - 1u))] = (uint8_t)(m * 32 + c);
            n2 += __popc(wv);
        }
        __syncwarp();
        if (c < DOUT) {
            const uint8_t* lst = lists[w];
            float p0 = 0.f, p1 = 0.f, p2 = 0.f, p3 = 0.f;
            int i = 0;
            for (; i + 4 <= n2; i += 4) {
                unsigned kk = *(const unsigned*)(lst + i);
                p0 += g_Wt_h2o[(kk & 255u) * DOUT + c];
                p1 += g_Wt_h2o[((kk >> 8) & 255u) * DOUT + c];
                p2 += g_Wt_h2o[((kk >> 16) & 255u) * DOUT + c];
                p3 += g_Wt_h2o[(kk >> 24) * DOUT + c];
            }
            for (; i < n2; i++) p0 += g_Wt_h2o[lst[i] * DOUT + c];
            oin_s[t * DOUT + c] = bo + ((p0 + p1) + (p2 + p3));
        }
        __syncwarp();
    }
    __syncthreads();

    // Phase B: serial mem_o scan (warp 0, identical arithmetic order)
    if (w == 0 && c < DOUT) {
        const float alpha_o = expf(-1.f / tau_m_o[c]);
        float mem_o = 0.f;
        for (int t = 0; t < T_; t++) {
            mem_o = mem_o * alpha_o + (1.f - alpha_o) * oin_s[t * DOUT + c];
            oin_s[t * DOUT + c] = mem_o;
        }
    }
    __syncthreads();

    // Phase C: parallel softmax over timesteps (warp w handles t = w, w+8, ...)
    {
        float acc = 0.f;
        for (int t = w; t < T_; t += 8) {
            float vv = (c < DOUT) ? oin_s[t * DOUT + c] : -1e30f;
            float mx = vv;
            #pragma unroll
            for (int s = 16; s > 0; s >>= 1)
                mx = fmaxf(mx, __shfl_xor_sync(0xffffffffu, mx, s));
            float e = (c < DOUT) ? expf(vv - mx) : 0.f;
            float sm = e;
            #pragma unroll
            for (int s = 16; s > 0; s >>= 1)
                sm += __shfl_xor_sync(0xffffffffu, sm, s);
            acc += e / sm;
        }
        if (c < DOUT) acc_part[w][c] = acc;
    }
    __syncthreads();

    if (w == 0 && c < DOUT) {
        float acc_o = 0.f;
        #pragma unroll
        for (int ww = 0; ww < 8; ww++) acc_o += acc_part[ww][c];
        out[bidx * DOUT + c] = acc_o;
    }
}

// ---------------------------------------------------------------------------
extern "C" void kernel_launch(void* const* d_in, const int* in_sizes, int n_in,
                              void* d_out, int out_size) {
    const float* x          = (const float*)d_in[0];
    const float* w_i2h1     = (const float*)d_in[1];
    const float* w_h12h1    = (const float*)d_in[2];
    const float* w_h12h2    = (const float*)d_in[3];
    const float* w_h22h2    = (const float*)d_in[4];
    const float* w_h2o      = (const float*)d_in[5];
    const float* b_h1       = (const float*)d_in[6];
    const float* b_h2       = (const float*)d_in[7];
    const float* b_o        = (const float*)d_in[8];
    const float* tau_adp_h1 = (const float*)d_in[9];
    const float* tau_adp_h2 = (const float*)d_in[10];
    const float* tau_m_h1   = (const float*)d_in[11];
    const float* tau_m_h2   = (const float*)d_in[12];
    const float* tau_m_o    = (const float*)d_in[13];

    cudaFuncSetAttribute(input_proj_kernel,
                         cudaFuncAttributeMaxDynamicSharedMemorySize, K1_SMEM);
    cudaFuncSetAttribute(recurrent_kernel,
                         cudaFuncAttributeMaxDynamicSharedMemorySize, SM_TOT);

    prep_kernel<<<(H1N * DIN + 255) / 256, 256>>>(w_i2h1, w_h12h1, w_h12h2,
                                                  w_h22h2, w_h2o);
    xlist_kernel<<<(B_ * T_) / 8, 256>>>(x);
    input_proj_kernel<<<dim3(8, 100), 256, K1_SMEM>>>();
    recurrent_kernel<<<B_, 256, SM_TOT>>>(b_h1, b_h2,
                                          tau_adp_h1, tau_adp_h2,
                                          tau_m_h1, tau_m_h2);
    out_kernel<<<B_, 256>>>(b_o, tau_m_o, (float*)d_out);
}

// round 13
// speedup vs baseline: 1.5408x; 1.0387x over previous
#include <cuda_runtime.h>
#include <cstdint>

#define B_    256
#define T_    250
#define DIN   700
#define H1N   256
#define H2N   256
#define DOUT  20
#define BJ0   0.01f
#define BETA_ 1.8f
#define XPAD  704

// ---------------- device globals (no allocations allowed) ------------------
__device__ float          g_I1[B_ * T_ * H1N];      // x @ w_i2h1.T
__device__ float          g_Wt_i2h1[DIN * H1N];     // [d][j]
__device__ float2         g_Wpair[H1N * H1N];       // [k][j] = (w11, w12)
__device__ float          g_Wt22[H2N * H2N];        // [k][j]
__device__ float          g_Wt_h2o[H2N * DOUT];     // [k][o]
__device__ unsigned short g_xlist[B_ * T_ * XPAD];
__device__ int            g_xcnt[B_ * T_];
__device__ uint32_t       g_m2[B_ * T_ * 8];        // layer-2 spike masks

// ---------------- PTX helpers ----------------------------------------------
__device__ __forceinline__ uint32_t smem_u32(const void* p) {
    uint32_t a;
    asm("{ .reg .u64 t; cvta.to.shared.u64 t, %1; cvt.u32.u64 %0, t; }"
        : "=r"(a) : "l"(p));
    return a;
}
__device__ __forceinline__ uint32_t ctarank() {
    uint32_t r; asm("mov.u32 %0, %%cluster_ctarank;" : "=r"(r)); return r;
}
#define MBAR_INIT(addr, cnt) \
    asm volatile("mbarrier.init.shared.b64 [%0], %1;" :: "r"(addr), "r"(cnt) : "memory")
#define ST_CLUSTER_V4(laddr, rnk, v) \
    asm volatile("{ .reg .b32 ra; mapa.shared::cluster.u32 ra, %0, %1; " \
                 "st.shared::cluster.v4.b32 [ra], {%2,%3,%4,%5}; }" \
                 :: "r"(laddr), "r"(rnk), "r"(v.x), "r"(v.y), "r"(v.z), "r"(v.w) \
                 : "memory")
#define MBAR_ARRIVE_CLUSTER(laddr, rnk) \
    asm volatile("{ .reg .b32 ra; mapa.shared::cluster.u32 ra, %0, %1; " \
                 "mbarrier.arrive.release.cluster.shared::cluster.b64 _, [ra]; }" \
                 :: "r"(laddr), "r"(rnk) : "memory")
#define MBAR_WAIT_PARITY_CLUSTER(laddr, ph) do {                               \
    uint32_t _done = 0;                                                        \
    while (!_done) {                                                           \
        asm volatile("{ .reg .pred p; "                                        \
            "mbarrier.try_wait.parity.acquire.cluster.shared::cta.b64 p, [%1], %2, 0x989680; " \
            "selp.b32 %0, 1, 0, p; }"                                          \
            : "=r"(_done) : "r"(laddr), "r"(ph) : "memory");                   \
    }                                                                          \
} while (0)
#define CLUSTER_SYNC_() do {                                                   \
    asm volatile("barrier.cluster.arrive.aligned;" ::: "memory");              \
    asm volatile("barrier.cluster.wait.aligned;" ::: "memory");                \
} while (0)

// ---------------------------------------------------------------------------
// K0: weight transposes / interleaving
// ---------------------------------------------------------------------------
__global__ void prep_kernel(const float* __restrict__ wi,
                            const float* __restrict__ w11,
                            const float* __restrict__ w12,
                            const float* __restrict__ w22,
                            const float* __restrict__ wo) {
    int idx = blockIdx.x * blockDim.x + threadIdx.x;
    if (idx < H1N * DIN) {
        int r = idx / DIN, c = idx % DIN;
        g_Wt_i2h1[c * H1N + r] = wi[idx];
    }
    if (idx < H1N * H1N) {
        int r = idx / H1N, c = idx % H1N;
        g_Wpair[c * H1N + r] = make_float2(w11[idx], w12[idx]);
        g_Wt22[c * H1N + r]  = w22[idx];
    }
    if (idx < DOUT * H2N) {
        int r = idx / H2N, c = idx % H2N;
        g_Wt_h2o[c * DOUT + r] = wo[idx];
    }
}

// ---------------------------------------------------------------------------
// K0b: per-sample active-input lists (ascending d), one warp per sample
// ---------------------------------------------------------------------------
__global__ __launch_bounds__(256) void xlist_kernel(const float* __restrict__ x) {
    int s    = blockIdx.x * 8 + (threadIdx.x >> 5);
    int lane = threadIdx.x & 31;
    if (s >= B_ * T_) return;
    const float* xr = x + (size_t)s * DIN;
    int cnt = 0;
    for (int base = 0; base < DIN; base += 32) {
        int d = base + lane;
        float v = (d < DIN) ? xr[d] : 0.f;
        unsigned m = __ballot_sync(0xffffffffu, v != 0.f);
        if (v != 0.f)
            g_xlist[(size_t)s * XPAD + cnt + __popc(m & ((1u << lane) - 1u))] =
                (unsigned short)d;
        cnt += __popc(m);
    }
    if (lane == 0) g_xcnt[s] = cnt;
}

// ---------------------------------------------------------------------------
// K1: input projection (R12 form — measured good). Two samples interleaved
// per warp, 1-deep index-block prefetch in the shared min-block.
// ---------------------------------------------------------------------------
#define K1_WT_BYTES  (DIN * 32 * 4)                   // 89600
#define K1_SMEM      (K1_WT_BYTES + 640 * 4)          // + counts

__global__ __launch_bounds__(256, 2) void input_proj_kernel() {
    extern __shared__ float wt[];                     // [700][32]
    int* cnt_s = (int*)((char*)wt + K1_WT_BYTES);     // [640]
    const int ct   = blockIdx.x;
    const int grp  = blockIdx.y;
    const int tid  = threadIdx.x;
    const int warp = tid >> 5;
    const int lane = tid & 31;

    for (int idx = tid; idx < DIN * 32; idx += 256) {
        int d = idx >> 5, c = idx & 31;
        wt[idx] = g_Wt_i2h1[d * H1N + ct * 32 + c];
    }
    for (int idx = tid; idx < 640; idx += 256)
        cnt_s[idx] = g_xcnt[grp * 640 + idx];
    __syncthreads();

    const int base = grp * 640 + warp * 80;
    for (int sp = 0; sp < 80; sp += 2) {
        const int s0 = base + sp, s1 = s0 + 1;
        const int n0 = cnt_s[warp * 80 + sp];
        const int n1 = cnt_s[warp * 80 + sp + 1];
        const unsigned short* l0 = g_xlist + (size_t)s0 * XPAD;
        const unsigned short* l1 = g_xlist + (size_t)s1 * XPAD;

        float a0 = 0.f, a1 = 0.f, a2 = 0.f, a3 = 0.f;
        float b0 = 0.f, b1 = 0.f, b2 = 0.f, b3 = 0.f;

        const int m = (n0 < n1 ? n0 : n1) & ~3;
        int i = 0;
        if (m >= 4) {
            ushort4 ka = *(const ushort4*)(l0);
            ushort4 kb = *(const ushort4*)(l1);
            for (; i + 8 <= m; i += 4) {
                ushort4 kan = *(const ushort4*)(l0 + i + 4);
                ushort4 kbn = *(const ushort4*)(l1 + i + 4);
                a0 += wt[ka.x * 32 + lane];
                b0 += wt[kb.x * 32 + lane];
                a1 += wt[ka.y * 32 + lane];
                b1 += wt[kb.y * 32 + lane];
                a2 += wt[ka.z * 32 + lane];
                b2 += wt[kb.z * 32 + lane];
                a3 += wt[ka.w * 32 + lane];
                b3 += wt[kb.w * 32 + lane];
                ka = kan; kb = kbn;
            }
            a0 += wt[ka.x * 32 + lane];
            b0 += wt[kb.x * 32 + lane];
            a1 += wt[ka.y * 32 + lane];
            b1 += wt[kb.y * 32 + lane];
            a2 += wt[ka.z * 32 + lane];
            b2 += wt[kb.z * 32 + lane];
            a3 += wt[ka.w * 32 + lane];
            b3 += wt[kb.w * 32 + lane];
            i += 4;
        }
        int ia = i;
        for (; ia + 4 <= n0; ia += 4) {
            ushort4 ka = *(const ushort4*)(l0 + ia);
            a0 += wt[ka.x * 32 + lane];
            a1 += wt[ka.y * 32 + lane];
            a2 += wt[ka.z * 32 + lane];
            a3 += wt[ka.w * 32 + lane];
        }
        for (; ia < n0; ia++) a0 += wt[l0[ia] * 32 + lane];
        int ib = i;
        for (; ib + 4 <= n1; ib += 4) {
            ushort4 kb = *(const ushort4*)(l1 + ib);
            b0 += wt[kb.x * 32 + lane];
            b1 += wt[kb.y * 32 + lane];
            b2 += wt[kb.z * 32 + lane];
            b3 += wt[kb.w * 32 + lane];
        }
        for (; ib < n1; ib++) b0 += wt[l1[ib] * 32 + lane];

        g_I1[(size_t)s0 * H1N + ct * 32 + lane] = (a0 + a1) + (a2 + a3);
        g_I1[(size_t)s1 * H1N + ct * 32 + lane] = (b0 + b1) + (b2 + b3);
    }
}

// ---------------------------------------------------------------------------
// K2: cluster-cooperative recurrent kernel — EXACT R11 form (measured 606us).
// Single exchange per step; full 8-window list-based gathers after the wait.
// ---------------------------------------------------------------------------
#define SM_WPAIR 0
#define SM_W22   65536
#define SM_L1    98304               // 8 * 256 bytes
#define SM_L2    100352              // 8 * 256 bytes
#define SM_STAGE 102400              // 16 u32 (16B aligned)
#define SM_MB    102464              // 2*8*16 u32 = 1024 B
#define SM_BAR   103488
#define SM_TOT   103504

__global__ __launch_bounds__(256, 2) __cluster_dims__(8, 1, 1)
void recurrent_kernel(
    const float* __restrict__ b_h1g, const float* __restrict__ b_h2g,
    const float* __restrict__ tau_adp_h1, const float* __restrict__ tau_adp_h2,
    const float* __restrict__ tau_m_h1,  const float* __restrict__ tau_m_h2) {

    extern __shared__ __align__(16) char smraw[];
    float2*         wpair_s = (float2*)(smraw + SM_WPAIR);   // [k*32+c]
    float*          w22_s   = (float*)(smraw + SM_W22);      // [k*32+c]
    uint8_t*        L1s     = (uint8_t*)(smraw + SM_L1);     // [b][256]
    uint8_t*        L2s     = (uint8_t*)(smraw + SM_L2);
    uint32_t*       stage   = (uint32_t*)(smraw + SM_STAGE); // [16]
    const uint32_t* mbw     = (const uint32_t*)(smraw + SM_MB);
    const uint32_t  smb     = smem_u32(smraw);
    const uint32_t  bar     = smb + SM_BAR;
    const uint32_t  mba     = smb + SM_MB;

    const int tid  = threadIdx.x;
    const int b    = tid >> 5;                 // warp = local batch
    const int c    = tid & 31;                 // lane = local column
    const uint32_t rank = ctarank();
    const int j    = rank * 32 + c;            // owned neuron
    const int gb   = (blockIdx.x >> 3) * 8 + b;

    for (int idx = tid; idx < H1N * 32; idx += 256) {
        int k = idx >> 5, cc = idx & 31;
        wpair_s[idx] = g_Wpair[k * H1N + rank * 32 + cc];
        w22_s[idx]   = g_Wt22[k * H1N + rank * 32 + cc];
    }
    if (tid == 0) MBAR_INIT(bar, 8);
    __syncthreads();
    CLUSTER_SYNC_();

    const float alpha1 = expf(-1.f / tau_m_h1[j]);
    const float ro1    = expf(-1.f / tau_adp_h1[j]);
    const float alpha2 = expf(-1.f / tau_m_h2[j]);
    const float ro2    = expf(-1.f / tau_adp_h2[j]);
    const float bh1    = b_h1g[j];
    const float bh2    = b_h2g[j];

    float mem1 = 0.f, spk1 = 0.f, bb1 = BJ0;
    float mem2 = 0.f, spk2 = 0.f, bb2 = BJ0;
    unsigned m2prev = 0u;

    const float* I1row = g_I1 + (size_t)gb * T_ * H1N;
    float s11 = I1row[j] + bh1;                // t=0: no recurrent terms

    uint8_t* L1b = L1s + b * 256;
    uint8_t* L2b = L2s + b * 256;
    uint32_t* m2out = g_m2 + (size_t)gb * T_ * 8 + rank;

    for (int t = 0; t < T_; t++) {
        const int par = t & 1;

        bb1  = ro1 * bb1 + BETA_ * (1.f - ro1) * spk1;
        mem1 = mem1 * alpha1 - bb1 * spk1 + (1.f - alpha1) * s11;
        spk1 = (mem1 - bb1 - BJ0 > 0.f) ? 1.f : 0.f;
        unsigned m1 = __ballot_sync(0xffffffffu, spk1 > 0.5f);

        if (c == 0) { stage[b] = m1; stage[8 + b] = m2prev; }
        __syncthreads();

        const int tn = (t + 1 < T_) ? (t + 1) : (T_ - 1);
        const float i1n = I1row[tn * H1N + j];

        if (b == 0 && c < 8) {
            const uint4* st4 = (const uint4*)stage;
            #pragma unroll
            for (int i = 0; i < 4; i++) {
                uint4 v = st4[i];
                uint32_t la = mba + (par * 128 + rank * 16 + i * 4) * 4;
                ST_CLUSTER_V4(la, (uint32_t)c, v);
            }
            MBAR_ARRIVE_CLUSTER(bar, (uint32_t)c);
        }
        MBAR_WAIT_PARITY_CLUSTER(bar, par);

        const uint32_t* mb = mbw + par * 128;

        int n2 = 0;
        #pragma unroll
        for (int m = 0; m < 8; m++) {
            unsigned w = mb[m * 16 + 8 + b];
            if (w & (1u << c))
                L2b[n2 + __popc(w & ((1u << c) - 1u))] = (uint8_t)(m * 32 + c);
            n2 += __popc(w);
        }
        int n1 = 0;
        #pragma unroll
        for (int m = 0; m < 8; m++) {
            unsigned w = mb[m * 16 + b];
            if (w & (1u << c))
                L1b[n1 + __popc(w & ((1u << c) - 1u))] = (uint8_t)(m * 32 + c);
            n1 += __popc(w);
        }
        __syncwarp();

        float a1p0 = 0.f, a1p1 = 0.f, a1p2 = 0.f, a1p3 = 0.f;
        float a2p0 = 0.f, a2p1 = 0.f, a2p2 = 0.f, a2p3 = 0.f;
        {
            int i = 0;
            for (; i + 4 <= n1; i += 4) {
                unsigned kk = *(const unsigned*)(L1b + i);
                float2 w0 = wpair_s[(kk & 255u) * 32 + c];
                float2 w1 = wpair_s[((kk >> 8) & 255u) * 32 + c];
                float2 w2 = wpair_s[((kk >> 16) & 255u) * 32 + c];
                float2 w3 = wpair_s[(kk >> 24) * 32 + c];
                a1p0 += w0.x; a2p0 += w0.y;
                a1p1 += w1.x; a2p1 += w1.y;
                a1p2 += w2.x; a2p2 += w2.y;
                a1p3 += w3.x; a2p3 += w3.y;
            }
            for (; i < n1; i++) {
                float2 w = wpair_s[L1b[i] * 32 + c];
                a1p0 += w.x; a2p0 += w.y;
            }
        }
        float a1 = (i1n + bh1) + ((a1p0 + a1p1) + (a1p2 + a1p3));
        float a2 = bh2 + ((a2p0 + a2p1) + (a2p2 + a2p3));

        float a3p0 = 0.f, a3p1 = 0.f, a3p2 = 0.f, a3p3 = 0.f;
        {
            int i = 0;
            for (; i + 4 <= n2; i += 4) {
                unsigned kk = *(const unsigned*)(L2b + i);
                a3p0 += w22_s[(kk & 255u) * 32 + c];
                a3p1 += w22_s[((kk >> 8) & 255u) * 32 + c];
                a3p2 += w22_s[((kk >> 16) & 255u) * 32 + c];
                a3p3 += w22_s[(kk >> 24) * 32 + c];
            }
            for (; i < n2; i++) a3p0 += w22_s[L2b[i] * 32 + c];
        }
        float a3 = (a3p0 + a3p1) + (a3p2 + a3p3);

        float h2 = a2 + a3;
        bb2  = ro2 * bb2 + BETA_ * (1.f - ro2) * spk2;
        mem2 = mem2 * alpha2 - bb2 * spk2 + (1.f - alpha2) * h2;
        spk2 = (mem2 - bb2 - BJ0 > 0.f) ? 1.f : 0.f;
        m2prev = __ballot_sync(0xffffffffu, spk2 > 0.5f);

        if (c == 0) m2out[t * 8] = m2prev;

        s11 = a1;
    }
    CLUSTER_SYNC_();
}

// ---------------------------------------------------------------------------
// K3 (fused, R12 form — measured good): Phase A: 8 warps compute oin[t,:]
// into smem. Phase B: warp 0 serial mem_o scan. Phase C: parallel softmax.
// ---------------------------------------------------------------------------
__global__ __launch_bounds__(256) void out_kernel(const float* __restrict__ b_og,
                                                  const float* __restrict__ tau_m_o,
                                                  float* __restrict__ out) {
    __shared__ float   oin_s[T_ * DOUT];        // 20 KB (reused for mem_o)
    __shared__ uint8_t lists[8][256];
    __shared__ float   acc_part[8][DOUT];

    const int bidx = blockIdx.x;
    const int w    = threadIdx.x >> 5;
    const int c    = threadIdx.x & 31;
    const float bo = (c < DOUT) ? b_og[c] : 0.f;

    const uint32_t* mbase = g_m2 + (size_t)bidx * T_ * 8;
    for (int t = w; t < T_; t += 8) {
        const uint32_t* mw = mbase + t * 8;
        int n2 = 0;
        #pragma unroll
        for (int m = 0; m < 8; m++) {
            unsigned wv = mw[m];
            if (wv & (1u << c))
                lists[w][n2 + __popc(wv & ((1u << c) - 1u))] = (uint8_t)(m * 32 + c);
            n2 += __popc(wv);
        }
        __syncwarp();
        if (c < DOUT) {
            const uint8_t* lst = lists[w];
            float p0 = 0.f, p1 = 0.f, p2 = 0.f, p3 = 0.f;
            int i = 0;
            for (; i + 4 <= n2; i += 4) {
                unsigned kk = *(const unsigned*)(lst + i);
                p0 += g_Wt_h2o[(kk & 255u) * DOUT + c];
                p1 += g_Wt_h2o[((kk >> 8) & 255u) * DOUT + c];
                p2 += g_Wt_h2o[((kk >> 16) & 255u) * DOUT + c];
                p3 += g_Wt_h2o[(kk >> 24) * DOUT + c];
            }
            for (; i < n2; i++) p0 += g_Wt_h2o[lst[i] * DOUT + c];
            oin_s[t * DOUT + c] = bo + ((p0 + p1) + (p2 + p3));
        }
        __syncwarp();
    }
    __syncthreads();

    if (w == 0 && c < DOUT) {
        const float alpha_o = expf(-1.f / tau_m_o[c]);
        float mem_o = 0.f;
        for (int t = 0; t < T_; t++) {
            mem_o = mem_o * alpha_o + (1.f - alpha_o) * oin_s[t * DOUT + c];
            oin_s[t * DOUT + c] = mem_o;
        }
    }
    __syncthreads();

    {
        float acc = 0.f;
        for (int t = w; t < T_; t += 8) {
            float vv = (c < DOUT) ? oin_s[t * DOUT + c] : -1e30f;
            float mx = vv;
            #pragma unroll
            for (int s = 16; s > 0; s >>= 1)
                mx = fmaxf(mx, __shfl_xor_sync(0xffffffffu, mx, s));
            float e = (c < DOUT) ? expf(vv - mx) : 0.f;
            float sm = e;
            #pragma unroll
            for (int s = 16; s > 0; s >>= 1)
                sm += __shfl_xor_sync(0xffffffffu, sm, s);
            acc += e / sm;
        }
        if (c < DOUT) acc_part[w][c] = acc;
    }
    __syncthreads();

    if (w == 0 && c < DOUT) {
        float acc_o = 0.f;
        #pragma unroll
        for (int ww = 0; ww < 8; ww++) acc_o += acc_part[ww][c];
        out[bidx * DOUT + c] = acc_o;
    }
}

// ---------------------------------------------------------------------------
extern "C" void kernel_launch(void* const* d_in, const int* in_sizes, int n_in,
                              void* d_out, int out_size) {
    const float* x          = (const float*)d_in[0];
    const float* w_i2h1     = (const float*)d_in[1];
    const float* w_h12h1    = (const float*)d_in[2];
    const float* w_h12h2    = (const float*)d_in[3];
    const float* w_h22h2    = (const float*)d_in[4];
    const float* w_h2o      = (const float*)d_in[5];
    const float* b_h1       = (const float*)d_in[6];
    const float* b_h2       = (const float*)d_in[7];
    const float* b_o        = (const float*)d_in[8];
    const float* tau_adp_h1 = (const float*)d_in[9];
    const float* tau_adp_h2 = (const float*)d_in[10];
    const float* tau_m_h1   = (const float*)d_in[11];
    const float* tau_m_h2   = (const float*)d_in[12];
    const float* tau_m_o    = (const float*)d_in[13];

    cudaFuncSetAttribute(input_proj_kernel,
                         cudaFuncAttributeMaxDynamicSharedMemorySize, K1_SMEM);
    cudaFuncSetAttribute(recurrent_kernel,
                         cudaFuncAttributeMaxDynamicSharedMemorySize, SM_TOT);

    prep_kernel<<<(H1N * DIN + 255) / 256, 256>>>(w_i2h1, w_h12h1, w_h12h2,
                                                  w_h22h2, w_h2o);
    xlist_kernel<<<(B_ * T_) / 8, 256>>>(x);
    input_proj_kernel<<<dim3(8, 100), 256, K1_SMEM>>>();
    recurrent_kernel<<<B_, 256, SM_TOT>>>(b_h1, b_h2,
                                          tau_adp_h1, tau_adp_h2,
                                          tau_m_h1, tau_m_h2);
    out_kernel<<<B_, 256>>>(b_o, tau_m_o, (float*)d_out);
}